// round 2
// baseline (speedup 1.0000x reference)
#include <cuda_runtime.h>
#include <cstdint>

#define NN 100000
#define NE 3200000
#define HID 128
#define OUTF 64

// ---------------- device scratch (static, no allocation) ----------------
__device__ int   g_is64;
__device__ int   g_degout[NN];
__device__ int   g_degin[NN];
__device__ float g_norms[NN];
__device__ float g_normd[NN];
__device__ int   g_rowptr[NN + 1];
__device__ int   g_cnt[NN];
__device__ int   g_col[NE];
__device__ float g_m[(size_t)NN * HID];   // aggregation output
__device__ float g_t[(size_t)NN * HID];   // post-activation
__device__ float g_z[(size_t)NN * OUTF];  // layer-3 pre-aggregation
__device__ float g_stats[512];            // [0..255] layer1 sum/sumsq, [256..511] layer2
__device__ float g_scale1[HID], g_shift1[HID];
__device__ float g_scale2[HID], g_shift2[HID];

// ---------------- helpers ----------------
__device__ __forceinline__ int edge_idx(const void* p, int e) {
    return g_is64 ? (int)((const long long*)p)[e] : ((const int*)p)[e];
}

__device__ __forceinline__ float4 affine4(float4 v, float4 sc, float4 sh) {
    float4 r;
    r.x = fmaf(v.x, sc.x, sh.x);
    r.y = fmaf(v.y, sc.y, sh.y);
    r.z = fmaf(v.z, sc.z, sh.z);
    r.w = fmaf(v.w, sc.w, sh.w);
    return r;
}

// ---------------- init / graph build ----------------
__global__ void zero_kernel() {
    int i = blockIdx.x * blockDim.x + threadIdx.x;
    if (i < NN) { g_degout[i] = 0; g_degin[i] = 0; }
    if (i < 512) g_stats[i] = 0.f;
}

__global__ void detect_kernel(const void* src) {
    if (threadIdx.x == 0 && blockIdx.x == 0) {
        const long long* p = (const long long*)src;
        int ok = 1;
        for (int i = 0; i < 128; i++) {
            long long v = p[i];
            if (v < 0 || v >= NN) { ok = 0; break; }
        }
        g_is64 = ok;
    }
}

__global__ void degree_kernel(const void* src, const void* dst) {
    int e = blockIdx.x * blockDim.x + threadIdx.x;
    if (e >= NE) return;
    atomicAdd(&g_degout[edge_idx(src, e)], 1);
    atomicAdd(&g_degin[edge_idx(dst, e)], 1);
}

__global__ void norm_kernel() {
    int i = blockIdx.x * blockDim.x + threadIdx.x;
    if (i >= NN) return;
    int dout = g_degout[i]; if (dout < 1) dout = 1;
    int din  = g_degin[i];  if (din  < 1) din  = 1;
    g_norms[i] = rsqrtf((float)dout);
    g_normd[i] = rsqrtf((float)din);
}

// single-block exclusive scan of deg_in -> rowptr, cnt
__global__ void scan_kernel() {
    __shared__ int sm[1024];
    int t = threadIdx.x;
    int carry = 0;
    for (int base = 0; base < NN; base += 1024) {
        int i = base + t;
        int v = (i < NN) ? g_degin[i] : 0;
        sm[t] = v;
        __syncthreads();
        #pragma unroll
        for (int off = 1; off < 1024; off <<= 1) {
            int x = (t >= off) ? sm[t - off] : 0;
            __syncthreads();
            sm[t] += x;
            __syncthreads();
        }
        int incl = sm[t];
        int excl = incl - v;
        if (i < NN) { g_rowptr[i] = carry + excl; g_cnt[i] = carry + excl; }
        int total = sm[1023];
        __syncthreads();
        carry += total;
    }
    if (t == 0) g_rowptr[NN] = carry;
}

__global__ void fill_kernel(const void* src, const void* dst) {
    int e = blockIdx.x * blockDim.x + threadIdx.x;
    if (e >= NE) return;
    int d = edge_idx(dst, e);
    int pos = atomicAdd(&g_cnt[d], 1);
    g_col[pos] = edge_idx(src, e);
}

// ---------------- SpMM: warp per destination node, 128 features ----------------
// out = g_m ;  h = (FIRST ? x : affine1(g_t)) scaled by norm_s per source row,
// result scaled by norm_d.
template<bool FIRST>
__global__ void __launch_bounds__(256) spmm128_kernel(const float* __restrict__ xin) {
    int t = blockIdx.x * 256 + threadIdx.x;
    int d = t >> 5;
    int lane = t & 31;
    if (d >= NN) return;
    const float* __restrict__ h = FIRST ? xin : g_t;
    int c = lane * 4;
    float4 sc = make_float4(0,0,0,0), sh = make_float4(0,0,0,0);
    if (!FIRST) {
        sc = *(const float4*)(g_scale1 + c);
        sh = *(const float4*)(g_shift1 + c);
    }
    int beg = g_rowptr[d], end = g_rowptr[d + 1];
    float ax = 0.f, ay = 0.f, az = 0.f, aw = 0.f;
    int j = beg;
    for (; j + 3 < end; j += 4) {
        int s0 = g_col[j], s1 = g_col[j + 1], s2 = g_col[j + 2], s3 = g_col[j + 3];
        float w0 = g_norms[s0], w1 = g_norms[s1], w2 = g_norms[s2], w3 = g_norms[s3];
        float4 v0 = *(const float4*)(h + (size_t)s0 * HID + c);
        float4 v1 = *(const float4*)(h + (size_t)s1 * HID + c);
        float4 v2 = *(const float4*)(h + (size_t)s2 * HID + c);
        float4 v3 = *(const float4*)(h + (size_t)s3 * HID + c);
        if (!FIRST) {
            v0 = affine4(v0, sc, sh); v1 = affine4(v1, sc, sh);
            v2 = affine4(v2, sc, sh); v3 = affine4(v3, sc, sh);
        }
        ax += w0 * v0.x + w1 * v1.x + w2 * v2.x + w3 * v3.x;
        ay += w0 * v0.y + w1 * v1.y + w2 * v2.y + w3 * v3.y;
        az += w0 * v0.z + w1 * v1.z + w2 * v2.z + w3 * v3.z;
        aw += w0 * v0.w + w1 * v1.w + w2 * v2.w + w3 * v3.w;
    }
    for (; j < end; j++) {
        int s = g_col[j];
        float w = g_norms[s];
        float4 v = *(const float4*)(h + (size_t)s * HID + c);
        if (!FIRST) v = affine4(v, sc, sh);
        ax += w * v.x; ay += w * v.y; az += w * v.z; aw += w * v.w;
    }
    float nd = g_normd[d];
    float4 o = make_float4(ax * nd, ay * nd, az * nd, aw * nd);
    *(float4*)(g_m + (size_t)d * HID + c) = o;
}

// ---------------- SpMM 64-wide + bias + log_softmax (final layer) ----------------
// z already includes norm_s (folded into the layer-3 GEMM A-load), so the
// gather here is UNWEIGHTED; only norm_d is applied at the end.
__global__ void __launch_bounds__(256) spmm64_kernel(const float* __restrict__ b3,
                                                     float* __restrict__ out) {
    int t = blockIdx.x * 256 + threadIdx.x;
    int d = t >> 5;
    int lane = t & 31;
    if (d >= NN) return;
    int c = lane * 2;
    int beg = g_rowptr[d], end = g_rowptr[d + 1];
    float a0 = 0.f, a1 = 0.f;
    int j = beg;
    for (; j + 3 < end; j += 4) {
        int s0 = g_col[j], s1 = g_col[j + 1], s2 = g_col[j + 2], s3 = g_col[j + 3];
        float2 v0 = *(const float2*)(g_z + (size_t)s0 * OUTF + c);
        float2 v1 = *(const float2*)(g_z + (size_t)s1 * OUTF + c);
        float2 v2 = *(const float2*)(g_z + (size_t)s2 * OUTF + c);
        float2 v3 = *(const float2*)(g_z + (size_t)s3 * OUTF + c);
        a0 += v0.x + v1.x + v2.x + v3.x;
        a1 += v0.y + v1.y + v2.y + v3.y;
    }
    for (; j < end; j++) {
        int s = g_col[j];
        float2 v = *(const float2*)(g_z + (size_t)s * OUTF + c);
        a0 += v.x; a1 += v.y;
    }
    float nd = g_normd[d];
    a0 = a0 * nd + b3[c];
    a1 = a1 * nd + b3[c + 1];
    // warp-wide log_softmax over 64 values (2 per lane)
    float mx = fmaxf(a0, a1);
    #pragma unroll
    for (int off = 16; off > 0; off >>= 1)
        mx = fmaxf(mx, __shfl_xor_sync(0xffffffffu, mx, off));
    float e = expf(a0 - mx) + expf(a1 - mx);
    #pragma unroll
    for (int off = 16; off > 0; off >>= 1)
        e += __shfl_xor_sync(0xffffffffu, e, off);
    float l = logf(e);
    out[(size_t)d * OUTF + c]     = a0 - mx - l;
    out[(size_t)d * OUTF + c + 1] = a1 - mx - l;
}

// ---------------- GEMM ----------------
// NC==128 : C = g_t = relu(g_m @ W + bias); accumulate BN stats at g_stats[stats_off..]
// NC==64  : C = g_z = ((g_t*scale2+shift2)*norm_s) @ W      (layer 3, no bias/stats)
template<int NC, bool STATS>
__global__ void __launch_bounds__(256)
gemm_kernel(const float* __restrict__ W, const float* __restrict__ bias, int stats_off) {
    constexpr bool TRANS = (NC == 64);
    const float* __restrict__ A = TRANS ? g_t : g_m;
    float* __restrict__ C = TRANS ? (float*)g_z : (float*)g_t;
    constexpr int CJ = NC / 16;  // cols per thread (8 or 4)

    __shared__ float As[128][33];     // [row][k], padded: conflict-free
    __shared__ float Bs[32][NC];      // [k][col]

    int tid = threadIdx.x;
    int tx = tid & 15, ty = tid >> 4;
    int row0 = blockIdx.x * 128;

    float acc[8][CJ];
    #pragma unroll
    for (int i = 0; i < 8; i++)
        #pragma unroll
        for (int j = 0; j < CJ; j++) acc[i][j] = 0.f;

    for (int kk = 0; kk < 128; kk += 32) {
        // load A tile: 128 rows x 32 k : 4 float4 per thread
        #pragma unroll
        for (int l = 0; l < 4; l++) {
            int idx = tid + l * 256;   // 0..1023
            int r = idx >> 3;          // 8 float4 per row
            int c4 = idx & 7;
            int grow = row0 + r;
            float4 v = make_float4(0, 0, 0, 0);
            if (grow < NN) v = *(const float4*)(A + (size_t)grow * 128 + kk + c4 * 4);
            if (TRANS) {
                int cb = kk + c4 * 4;
                float ns = (grow < NN) ? g_norms[grow] : 0.f;
                v.x = fmaf(v.x, g_scale2[cb + 0], g_shift2[cb + 0]) * ns;
                v.y = fmaf(v.y, g_scale2[cb + 1], g_shift2[cb + 1]) * ns;
                v.z = fmaf(v.z, g_scale2[cb + 2], g_shift2[cb + 2]) * ns;
                v.w = fmaf(v.w, g_scale2[cb + 3], g_shift2[cb + 3]) * ns;
            }
            As[r][c4 * 4 + 0] = v.x;
            As[r][c4 * 4 + 1] = v.y;
            As[r][c4 * 4 + 2] = v.z;
            As[r][c4 * 4 + 3] = v.w;
        }
        // load B tile: 32 x NC
        constexpr int BL = 32 * NC / (256 * 4);
        #pragma unroll
        for (int l = 0; l < BL; l++) {
            int idx = tid + l * 256;
            int k = idx / (NC / 4);
            int c4 = idx % (NC / 4);
            float4 v = *(const float4*)(W + (size_t)(kk + k) * NC + c4 * 4);
            *(float4*)(&Bs[k][c4 * 4]) = v;
        }
        __syncthreads();
        #pragma unroll
        for (int k = 0; k < 32; k++) {
            float a[8], b[CJ];
            #pragma unroll
            for (int i = 0; i < 8; i++) a[i] = As[ty * 8 + i][k];
            #pragma unroll
            for (int j = 0; j < CJ; j += 4) {
                float4 bv = *(const float4*)(&Bs[k][tx * CJ + j]);
                b[j] = bv.x; b[j + 1] = bv.y; b[j + 2] = bv.z; b[j + 3] = bv.w;
            }
            #pragma unroll
            for (int i = 0; i < 8; i++)
                #pragma unroll
                for (int j = 0; j < CJ; j++)
                    acc[i][j] = fmaf(a[i], b[j], acc[i][j]);
        }
        __syncthreads();
    }

    // epilogue
    float bb[CJ];
    if (STATS) {
        #pragma unroll
        for (int j = 0; j < CJ; j++) bb[j] = bias[tx * CJ + j];
    }
    float psum[CJ], psq[CJ];
    #pragma unroll
    for (int j = 0; j < CJ; j++) { psum[j] = 0.f; psq[j] = 0.f; }

    #pragma unroll
    for (int i = 0; i < 8; i++) {
        int grow = row0 + ty * 8 + i;
        if (grow < NN) {
            float vout[CJ];
            #pragma unroll
            for (int j = 0; j < CJ; j++) {
                float v = acc[i][j];
                if (STATS) {
                    v += bb[j];
                    v = fmaxf(v, 0.f);
                    psum[j] += v;
                    psq[j] += v * v;
                }
                vout[j] = v;
            }
            float* cp = C + (size_t)grow * NC + tx * CJ;
            #pragma unroll
            for (int j = 0; j < CJ; j += 4)
                *(float4*)(cp + j) = make_float4(vout[j], vout[j + 1], vout[j + 2], vout[j + 3]);
        }
    }

    if (STATS) {
        __syncthreads();
        float* p = &As[0][0];        // reuse smem: 16*NC sums + 16*NC sumsq (4096 <= 4224)
        float* ssum = p;
        float* ssq = p + 16 * NC;
        #pragma unroll
        for (int j = 0; j < CJ; j++) {
            ssum[ty * NC + tx * CJ + j] = psum[j];
            ssq [ty * NC + tx * CJ + j] = psq[j];
        }
        __syncthreads();
        if (tid < NC) {
            float s = 0.f, q = 0.f;
            #pragma unroll
            for (int r = 0; r < 16; r++) { s += ssum[r * NC + tid]; q += ssq[r * NC + tid]; }
            atomicAdd(&g_stats[stats_off + tid], s);
            atomicAdd(&g_stats[stats_off + NC + tid], q);
        }
    }
}

// ---------------- BN finalize ----------------
__global__ void bnfin_kernel(const float* __restrict__ gamma, const float* __restrict__ beta,
                             int stats_off, int which) {
    int c = threadIdx.x;
    if (c < HID) {
        float inv_n = 1.0f / (float)NN;
        float mean = g_stats[stats_off + c] * inv_n;
        float var = g_stats[stats_off + HID + c] * inv_n - mean * mean;
        float sc = gamma[c] * rsqrtf(var + 1e-5f);
        float sh = beta[c] - mean * sc;
        if (which == 1) { g_scale1[c] = sc; g_shift1[c] = sh; }
        else            { g_scale2[c] = sc; g_shift2[c] = sh; }
    }
}

// ---------------- launch ----------------
extern "C" void kernel_launch(void* const* d_in, const int* in_sizes, int n_in,
                              void* d_out, int out_size) {
    const float* x      = (const float*)d_in[0];
    const void*  src    = d_in[1];
    const void*  dst    = d_in[2];
    const float* W1     = (const float*)d_in[3];
    const float* b1     = (const float*)d_in[4];
    const float* W2     = (const float*)d_in[5];
    const float* b2     = (const float*)d_in[6];
    const float* W3     = (const float*)d_in[7];
    const float* b3     = (const float*)d_in[8];
    const float* gamma1 = (const float*)d_in[9];
    const float* beta1  = (const float*)d_in[10];
    const float* gamma2 = (const float*)d_in[11];
    const float* beta2  = (const float*)d_in[12];
    float* out = (float*)d_out;

    const int NB  = (NN + 255) / 256;       // 391
    const int EB  = (NE + 255) / 256;       // 12500
    const int WB  = (NN * 32) / 256;        // 12500 (warp per node)
    const int GB  = (NN + 127) / 128;       // 782

    zero_kernel<<<NB, 256>>>();
    detect_kernel<<<1, 32>>>(src);
    degree_kernel<<<EB, 256>>>(src, dst);
    norm_kernel<<<NB, 256>>>();
    scan_kernel<<<1, 1024>>>();
    fill_kernel<<<EB, 256>>>(src, dst);

    // layer 1
    spmm128_kernel<true><<<WB, 256>>>(x);
    gemm_kernel<128, true><<<GB, 256>>>(W1, b1, 0);
    bnfin_kernel<<<1, 128>>>(gamma1, beta1, 0, 1);

    // layer 2 (BN1 affine fused into gather)
    spmm128_kernel<false><<<WB, 256>>>(nullptr);
    gemm_kernel<128, true><<<GB, 256>>>(W2, b2, 256);
    bnfin_kernel<<<1, 128>>>(gamma2, beta2, 256, 2);

    // layer 3: GEMM first (128->64), then 64-wide aggregation + bias + log_softmax
    gemm_kernel<64, false><<<GB, 256>>>(W3, nullptr, 0);
    spmm64_kernel<<<WB, 256>>>(b3, out);
}

// round 3
// speedup vs baseline: 1.1963x; 1.1963x over previous
#include <cuda_runtime.h>
#include <cstdint>

#define NN 100000
#define NE 3200000
#define HID 128
#define OUTF 64
#define SCAN_NB 391   // ceil(NN/256)

// ---------------- device scratch (static, no allocation) ----------------
__device__ int   g_is64;
__device__ int   g_degout[NN];
__device__ int   g_degin[NN];
__device__ float g_norms[NN];
__device__ float g_normd[NN];
__device__ int   g_rowptr[NN + 1];
__device__ int   g_cnt[NN];
__device__ int   g_srci[NE];
__device__ int   g_dsti[NE];
__device__ int   g_col[NE];
__device__ unsigned long long g_scanstate[SCAN_NB];
__device__ float g_m[(size_t)NN * HID];   // aggregation output
__device__ float g_t[(size_t)NN * HID];   // post-activation
__device__ float g_z[(size_t)NN * OUTF];  // layer-3 pre-aggregation
__device__ float g_stats[512];            // [0..255] layer1 sum/sumsq, [256..511] layer2
__device__ float g_scale1[HID], g_shift1[HID];
__device__ float g_scale2[HID], g_shift2[HID];

// ---------------- helpers ----------------
__device__ __forceinline__ float4 affine4(float4 v, float4 sc, float4 sh) {
    float4 r;
    r.x = fmaf(v.x, sc.x, sh.x);
    r.y = fmaf(v.y, sc.y, sh.y);
    r.z = fmaf(v.z, sc.z, sh.z);
    r.w = fmaf(v.w, sc.w, sh.w);
    return r;
}

// ---------------- init: zero counters + dtype detect ----------------
__global__ void init_kernel(const void* src) {
    int i = blockIdx.x * blockDim.x + threadIdx.x;
    if (i < NN) { g_degout[i] = 0; g_degin[i] = 0; }
    if (i < 512) g_stats[i] = 0.f;
    if (i < SCAN_NB) g_scanstate[i] = 0ull;
    if (i == 0) {
        const long long* p = (const long long*)src;
        int ok = 1;
        #pragma unroll 1
        for (int k = 0; k < 128; k++) {
            long long v = p[k];
            if (v < 0 || v >= NN) { ok = 0; break; }
        }
        g_is64 = ok;
    }
}

// ---------------- degrees + int32 conversion (single pass over int64) ----------------
__global__ void degree_kernel(const void* src, const void* dst) {
    int e = blockIdx.x * blockDim.x + threadIdx.x;
    if (e >= NE) return;
    int is64 = g_is64;
    int s = is64 ? (int)((const long long*)src)[e] : ((const int*)src)[e];
    int d = is64 ? (int)((const long long*)dst)[e] : ((const int*)dst)[e];
    g_srci[e] = s;
    g_dsti[e] = d;
    atomicAdd(&g_degout[s], 1);
    atomicAdd(&g_degin[d], 1);
}

// ---------------- single-pass scan (decoupled lookback) + norms ----------------
// state word: [flag(2b) << 32 | value]; flag 1 = aggregate, 2 = inclusive prefix
__global__ void __launch_bounds__(256) scan_kernel() {
    int bid = blockIdx.x;
    int t = threadIdx.x;
    int lane = t & 31, wid = t >> 5;
    int i = bid * 256 + t;
    int v = (i < NN) ? g_degin[i] : 0;

    // warp inclusive scan
    int x = v;
    #pragma unroll
    for (int off = 1; off < 32; off <<= 1) {
        int y = __shfl_up_sync(0xffffffffu, x, off);
        if (lane >= off) x += y;
    }
    __shared__ int wsum[8];
    if (lane == 31) wsum[wid] = x;
    __syncthreads();
    if (wid == 0 && lane < 8) {
        int w = wsum[lane];
        #pragma unroll
        for (int off = 1; off < 8; off <<= 1) {
            int y = __shfl_up_sync(0xffu, w, off);
            if (lane >= off) w += y;
        }
        wsum[lane] = w;
    }
    __syncthreads();
    int incl = x + (wid > 0 ? wsum[wid - 1] : 0);
    int bsum = wsum[7];

    __shared__ int s_excl;
    if (t == 0) {
        if (bid == 0) {
            atomicExch(&g_scanstate[0], (2ull << 32) | (unsigned long long)(unsigned)bsum);
            s_excl = 0;
        } else {
            atomicExch(&g_scanstate[bid], (1ull << 32) | (unsigned long long)(unsigned)bsum);
            long long running = 0;
            int j = bid - 1;
            while (true) {
                unsigned long long st = atomicAdd(&g_scanstate[j], 0ull);
                unsigned f = (unsigned)(st >> 32);
                if (f == 0u) continue;
                running += (long long)(unsigned)st;
                if (f == 2u) break;
                j--;
            }
            s_excl = (int)running;
            atomicExch(&g_scanstate[bid],
                       (2ull << 32) | (unsigned long long)(unsigned)(running + bsum));
        }
    }
    __syncthreads();
    int base = s_excl;
    if (i < NN) {
        int r = base + incl - v;
        g_rowptr[i] = r;
        g_cnt[i] = r;
        int dout = g_degout[i]; if (dout < 1) dout = 1;
        int din = v; if (din < 1) din = 1;
        g_norms[i] = rsqrtf((float)dout);
        g_normd[i] = rsqrtf((float)din);
        if (i == NN - 1) g_rowptr[NN] = r + v;
    }
}

__global__ void fill_kernel() {
    int e = blockIdx.x * blockDim.x + threadIdx.x;
    if (e >= NE) return;
    int d = g_dsti[e];
    int pos = atomicAdd(&g_cnt[d], 1);
    g_col[pos] = g_srci[e];
}

// ---------------- SpMM: warp per destination node, 128 features ----------------
template<bool FIRST>
__global__ void __launch_bounds__(256) spmm128_kernel(const float* __restrict__ xin) {
    int t = blockIdx.x * 256 + threadIdx.x;
    int d = t >> 5;
    int lane = t & 31;
    if (d >= NN) return;
    const float* __restrict__ h = FIRST ? xin : g_t;
    int c = lane * 4;
    float4 sc = make_float4(0,0,0,0), sh = make_float4(0,0,0,0);
    if (!FIRST) {
        sc = *(const float4*)(g_scale1 + c);
        sh = *(const float4*)(g_shift1 + c);
    }
    int beg = g_rowptr[d], end = g_rowptr[d + 1];
    float ax = 0.f, ay = 0.f, az = 0.f, aw = 0.f;
    int j = beg;
    for (; j + 3 < end; j += 4) {
        int s0 = g_col[j], s1 = g_col[j + 1], s2 = g_col[j + 2], s3 = g_col[j + 3];
        float w0 = g_norms[s0], w1 = g_norms[s1], w2 = g_norms[s2], w3 = g_norms[s3];
        float4 v0 = *(const float4*)(h + (size_t)s0 * HID + c);
        float4 v1 = *(const float4*)(h + (size_t)s1 * HID + c);
        float4 v2 = *(const float4*)(h + (size_t)s2 * HID + c);
        float4 v3 = *(const float4*)(h + (size_t)s3 * HID + c);
        if (!FIRST) {
            v0 = affine4(v0, sc, sh); v1 = affine4(v1, sc, sh);
            v2 = affine4(v2, sc, sh); v3 = affine4(v3, sc, sh);
        }
        ax += w0 * v0.x + w1 * v1.x + w2 * v2.x + w3 * v3.x;
        ay += w0 * v0.y + w1 * v1.y + w2 * v2.y + w3 * v3.y;
        az += w0 * v0.z + w1 * v1.z + w2 * v2.z + w3 * v3.z;
        aw += w0 * v0.w + w1 * v1.w + w2 * v2.w + w3 * v3.w;
    }
    for (; j < end; j++) {
        int s = g_col[j];
        float w = g_norms[s];
        float4 v = *(const float4*)(h + (size_t)s * HID + c);
        if (!FIRST) v = affine4(v, sc, sh);
        ax += w * v.x; ay += w * v.y; az += w * v.z; aw += w * v.w;
    }
    float nd = g_normd[d];
    float4 o = make_float4(ax * nd, ay * nd, az * nd, aw * nd);
    *(float4*)(g_m + (size_t)d * HID + c) = o;
}

// ---------------- SpMM 64-wide + bias + log_softmax (final layer) ----------------
// z already includes norm_s (folded into the layer-3 GEMM A-load):
// unweighted gather; only norm_d applied at the end.
__global__ void __launch_bounds__(256) spmm64_kernel(const float* __restrict__ b3,
                                                     float* __restrict__ out) {
    int t = blockIdx.x * 256 + threadIdx.x;
    int d = t >> 5;
    int lane = t & 31;
    if (d >= NN) return;
    int c = lane * 2;
    int beg = g_rowptr[d], end = g_rowptr[d + 1];
    float a0 = 0.f, a1 = 0.f;
    int j = beg;
    for (; j + 3 < end; j += 4) {
        int s0 = g_col[j], s1 = g_col[j + 1], s2 = g_col[j + 2], s3 = g_col[j + 3];
        float2 v0 = *(const float2*)(g_z + (size_t)s0 * OUTF + c);
        float2 v1 = *(const float2*)(g_z + (size_t)s1 * OUTF + c);
        float2 v2 = *(const float2*)(g_z + (size_t)s2 * OUTF + c);
        float2 v3 = *(const float2*)(g_z + (size_t)s3 * OUTF + c);
        a0 += v0.x + v1.x + v2.x + v3.x;
        a1 += v0.y + v1.y + v2.y + v3.y;
    }
    for (; j < end; j++) {
        int s = g_col[j];
        float2 v = *(const float2*)(g_z + (size_t)s * OUTF + c);
        a0 += v.x; a1 += v.y;
    }
    float nd = g_normd[d];
    a0 = a0 * nd + b3[c];
    a1 = a1 * nd + b3[c + 1];
    float mx = fmaxf(a0, a1);
    #pragma unroll
    for (int off = 16; off > 0; off >>= 1)
        mx = fmaxf(mx, __shfl_xor_sync(0xffffffffu, mx, off));
    float e = expf(a0 - mx) + expf(a1 - mx);
    #pragma unroll
    for (int off = 16; off > 0; off >>= 1)
        e += __shfl_xor_sync(0xffffffffu, e, off);
    float l = logf(e);
    out[(size_t)d * OUTF + c]     = a0 - mx - l;
    out[(size_t)d * OUTF + c + 1] = a1 - mx - l;
}

// ---------------- GEMM ----------------
// NC==128 : g_t = relu(g_m @ W + bias); accumulate BN stats at g_stats[stats_off..]
// NC==64  : g_z = ((g_t*scale2+shift2)*norm_s) @ W   (layer 3)
template<int NC, bool STATS>
__global__ void __launch_bounds__(256)
gemm_kernel(const float* __restrict__ W, const float* __restrict__ bias, int stats_off) {
    constexpr bool TRANS = (NC == 64);
    const float* __restrict__ A = TRANS ? g_t : g_m;
    float* __restrict__ C = TRANS ? (float*)g_z : (float*)g_t;
    constexpr int CJ = NC / 16;

    __shared__ float As[128][33];
    __shared__ float Bs[32][NC];

    int tid = threadIdx.x;
    int tx = tid & 15, ty = tid >> 4;
    int row0 = blockIdx.x * 128;

    float acc[8][CJ];
    #pragma unroll
    for (int i = 0; i < 8; i++)
        #pragma unroll
        for (int j = 0; j < CJ; j++) acc[i][j] = 0.f;

    for (int kk = 0; kk < 128; kk += 32) {
        #pragma unroll
        for (int l = 0; l < 4; l++) {
            int idx = tid + l * 256;
            int r = idx >> 3;
            int c4 = idx & 7;
            int grow = row0 + r;
            float4 v = make_float4(0, 0, 0, 0);
            if (grow < NN) v = *(const float4*)(A + (size_t)grow * 128 + kk + c4 * 4);
            if (TRANS) {
                int cb = kk + c4 * 4;
                float ns = (grow < NN) ? g_norms[grow] : 0.f;
                v.x = fmaf(v.x, g_scale2[cb + 0], g_shift2[cb + 0]) * ns;
                v.y = fmaf(v.y, g_scale2[cb + 1], g_shift2[cb + 1]) * ns;
                v.z = fmaf(v.z, g_scale2[cb + 2], g_shift2[cb + 2]) * ns;
                v.w = fmaf(v.w, g_scale2[cb + 3], g_shift2[cb + 3]) * ns;
            }
            As[r][c4 * 4 + 0] = v.x;
            As[r][c4 * 4 + 1] = v.y;
            As[r][c4 * 4 + 2] = v.z;
            As[r][c4 * 4 + 3] = v.w;
        }
        constexpr int BL = 32 * NC / (256 * 4);
        #pragma unroll
        for (int l = 0; l < BL; l++) {
            int idx = tid + l * 256;
            int k = idx / (NC / 4);
            int c4 = idx % (NC / 4);
            float4 v = *(const float4*)(W + (size_t)(kk + k) * NC + c4 * 4);
            *(float4*)(&Bs[k][c4 * 4]) = v;
        }
        __syncthreads();
        #pragma unroll
        for (int k = 0; k < 32; k++) {
            float a[8], b[CJ];
            #pragma unroll
            for (int i = 0; i < 8; i++) a[i] = As[ty * 8 + i][k];
            #pragma unroll
            for (int j = 0; j < CJ; j += 4) {
                float4 bv = *(const float4*)(&Bs[k][tx * CJ + j]);
                b[j] = bv.x; b[j + 1] = bv.y; b[j + 2] = bv.z; b[j + 3] = bv.w;
            }
            #pragma unroll
            for (int i = 0; i < 8; i++)
                #pragma unroll
                for (int j = 0; j < CJ; j++)
                    acc[i][j] = fmaf(a[i], b[j], acc[i][j]);
        }
        __syncthreads();
    }

    float bb[CJ];
    if (STATS) {
        #pragma unroll
        for (int j = 0; j < CJ; j++) bb[j] = bias[tx * CJ + j];
    }
    float psum[CJ], psq[CJ];
    #pragma unroll
    for (int j = 0; j < CJ; j++) { psum[j] = 0.f; psq[j] = 0.f; }

    #pragma unroll
    for (int i = 0; i < 8; i++) {
        int grow = row0 + ty * 8 + i;
        if (grow < NN) {
            float vout[CJ];
            #pragma unroll
            for (int j = 0; j < CJ; j++) {
                float v = acc[i][j];
                if (STATS) {
                    v += bb[j];
                    v = fmaxf(v, 0.f);
                    psum[j] += v;
                    psq[j] += v * v;
                }
                vout[j] = v;
            }
            float* cp = C + (size_t)grow * NC + tx * CJ;
            #pragma unroll
            for (int j = 0; j < CJ; j += 4)
                *(float4*)(cp + j) = make_float4(vout[j], vout[j + 1], vout[j + 2], vout[j + 3]);
        }
    }

    if (STATS) {
        __syncthreads();
        float* p = &As[0][0];
        float* ssum = p;
        float* ssq = p + 16 * NC;
        #pragma unroll
        for (int j = 0; j < CJ; j++) {
            ssum[ty * NC + tx * CJ + j] = psum[j];
            ssq [ty * NC + tx * CJ + j] = psq[j];
        }
        __syncthreads();
        if (tid < NC) {
            float s = 0.f, q = 0.f;
            #pragma unroll
            for (int r = 0; r < 16; r++) { s += ssum[r * NC + tid]; q += ssq[r * NC + tid]; }
            atomicAdd(&g_stats[stats_off + tid], s);
            atomicAdd(&g_stats[stats_off + NC + tid], q);
        }
    }
}

// ---------------- BN finalize ----------------
__global__ void bnfin_kernel(const float* __restrict__ gamma, const float* __restrict__ beta,
                             int stats_off, int which) {
    int c = threadIdx.x;
    if (c < HID) {
        float inv_n = 1.0f / (float)NN;
        float mean = g_stats[stats_off + c] * inv_n;
        float var = g_stats[stats_off + HID + c] * inv_n - mean * mean;
        float sc = gamma[c] * rsqrtf(var + 1e-5f);
        float sh = beta[c] - mean * sc;
        if (which == 1) { g_scale1[c] = sc; g_shift1[c] = sh; }
        else            { g_scale2[c] = sc; g_shift2[c] = sh; }
    }
}

// ---------------- launch ----------------
extern "C" void kernel_launch(void* const* d_in, const int* in_sizes, int n_in,
                              void* d_out, int out_size) {
    const float* x      = (const float*)d_in[0];
    const void*  src    = d_in[1];
    const void*  dst    = d_in[2];
    const float* W1     = (const float*)d_in[3];
    const float* b1     = (const float*)d_in[4];
    const float* W2     = (const float*)d_in[5];
    const float* b2     = (const float*)d_in[6];
    const float* W3     = (const float*)d_in[7];
    const float* b3     = (const float*)d_in[8];
    const float* gamma1 = (const float*)d_in[9];
    const float* beta1  = (const float*)d_in[10];
    const float* gamma2 = (const float*)d_in[11];
    const float* beta2  = (const float*)d_in[12];
    float* out = (float*)d_out;

    const int NB  = (NN + 255) / 256;       // 391
    const int EB  = (NE + 255) / 256;       // 12500
    const int WB  = (NN * 32) / 256;        // 12500 (warp per node)
    const int GB  = (NN + 127) / 128;       // 782

    init_kernel<<<NB, 256>>>(src);
    degree_kernel<<<EB, 256>>>(src, dst);
    scan_kernel<<<SCAN_NB, 256>>>();
    fill_kernel<<<EB, 256>>>();

    // layer 1
    spmm128_kernel<true><<<WB, 256>>>(x);
    gemm_kernel<128, true><<<GB, 256>>>(W1, b1, 0);
    bnfin_kernel<<<1, 128>>>(gamma1, beta1, 0, 1);

    // layer 2 (BN1 affine fused into gather)
    spmm128_kernel<false><<<WB, 256>>>(nullptr);
    gemm_kernel<128, true><<<GB, 256>>>(W2, b2, 256);
    bnfin_kernel<<<1, 128>>>(gamma2, beta2, 256, 2);

    // layer 3: GEMM first (128->64), then 64-wide aggregation + bias + log_softmax
    gemm_kernel<64, false><<<GB, 256>>>(W3, nullptr, 0);
    spmm64_kernel<<<WB, 256>>>(b3, out);
}

// round 5
// speedup vs baseline: 1.2639x; 1.0565x over previous
#include <cuda_runtime.h>
#include <cuda_fp16.h>
#include <cstdint>

#define NN 100000
#define NE 3200000
#define HID 128
#define OUTF 64
#define SCAN_NB 391   // ceil(NN/256)

// ---------------- device scratch (static, no allocation) ----------------
__device__ int    g_is64;
__device__ int    g_degout[NN];
__device__ int    g_degin[NN];
__device__ float  g_norms[NN];
__device__ float  g_normd[NN];
__device__ int    g_rowptr[NN + 1];
__device__ int    g_cnt[NN];
__device__ int    g_srci[NE];
__device__ int    g_dsti[NE];
__device__ int    g_col[NE];
__device__ unsigned long long g_scanstate[SCAN_NB];
__device__ float  g_m[(size_t)NN * HID];    // aggregation output (fp32)
__device__ float  g_t[(size_t)NN * HID];    // relu output (fp32)
__device__ __half g_x16[(size_t)NN * HID];  // x * norm_s (fp16), layer-1 gather operand
__device__ __half g_z16[(size_t)NN * OUTF]; // layer-3 pre-aggregation (fp16)
__device__ float  g_stats[512];
__device__ float  g_scale1[HID], g_shift1[HID];
__device__ float  g_scale2[HID], g_shift2[HID];

// ---------------- helpers ----------------
__device__ __forceinline__ float4 affine4(float4 v, float4 sc, float4 sh) {
    float4 r;
    r.x = fmaf(v.x, sc.x, sh.x);
    r.y = fmaf(v.y, sc.y, sh.y);
    r.z = fmaf(v.z, sc.z, sh.z);
    r.w = fmaf(v.w, sc.w, sh.w);
    return r;
}

// ---------------- init: zero counters + dtype detect ----------------
__global__ void init_kernel(const void* src) {
    int i = blockIdx.x * blockDim.x + threadIdx.x;
    if (i < NN) { g_degout[i] = 0; g_degin[i] = 0; }
    if (i < 512) g_stats[i] = 0.f;
    if (i < SCAN_NB) g_scanstate[i] = 0ull;
    if (i == 0) {
        const long long* p = (const long long*)src;
        int ok = 1;
        #pragma unroll 1
        for (int k = 0; k < 128; k++) {
            long long v = p[k];
            if (v < 0 || v >= NN) { ok = 0; break; }
        }
        g_is64 = ok;
    }
}

// ---------------- degrees + int32 conversion ----------------
__global__ void degree_kernel(const void* src, const void* dst) {
    int e = blockIdx.x * blockDim.x + threadIdx.x;
    if (e >= NE) return;
    int is64 = g_is64;
    int s = is64 ? (int)((const long long*)src)[e] : ((const int*)src)[e];
    int d = is64 ? (int)((const long long*)dst)[e] : ((const int*)dst)[e];
    g_srci[e] = s;
    g_dsti[e] = d;
    atomicAdd(&g_degout[s], 1);
    atomicAdd(&g_degin[d], 1);
}

// ---------------- single-pass scan (decoupled lookback) + norms ----------------
__global__ void __launch_bounds__(256) scan_kernel() {
    int bid = blockIdx.x;
    int t = threadIdx.x;
    int lane = t & 31, wid = t >> 5;
    int i = bid * 256 + t;
    int v = (i < NN) ? g_degin[i] : 0;

    int x = v;
    #pragma unroll
    for (int off = 1; off < 32; off <<= 1) {
        int y = __shfl_up_sync(0xffffffffu, x, off);
        if (lane >= off) x += y;
    }
    __shared__ int wsum[8];
    if (lane == 31) wsum[wid] = x;
    __syncthreads();
    if (wid == 0 && lane < 8) {
        int w = wsum[lane];
        #pragma unroll
        for (int off = 1; off < 8; off <<= 1) {
            int y = __shfl_up_sync(0xffu, w, off);
            if (lane >= off) w += y;
        }
        wsum[lane] = w;
    }
    __syncthreads();
    int incl = x + (wid > 0 ? wsum[wid - 1] : 0);
    int bsum = wsum[7];

    __shared__ int s_excl;
    if (t == 0) {
        if (bid == 0) {
            atomicExch(&g_scanstate[0], (2ull << 32) | (unsigned long long)(unsigned)bsum);
            s_excl = 0;
        } else {
            atomicExch(&g_scanstate[bid], (1ull << 32) | (unsigned long long)(unsigned)bsum);
            long long running = 0;
            int j = bid - 1;
            while (true) {
                unsigned long long st = atomicAdd(&g_scanstate[j], 0ull);
                unsigned f = (unsigned)(st >> 32);
                if (f == 0u) continue;
                running += (long long)(unsigned)st;
                if (f == 2u) break;
                j--;
            }
            s_excl = (int)running;
            atomicExch(&g_scanstate[bid],
                       (2ull << 32) | (unsigned long long)(unsigned)(running + bsum));
        }
    }
    __syncthreads();
    int base = s_excl;
    if (i < NN) {
        int r = base + incl - v;
        g_rowptr[i] = r;
        g_cnt[i] = r;
        int dout = g_degout[i]; if (dout < 1) dout = 1;
        int din = v; if (din < 1) din = 1;
        g_norms[i] = rsqrtf((float)dout);
        g_normd[i] = rsqrtf((float)din);
        if (i == NN - 1) g_rowptr[NN] = r + v;
    }
}

__global__ void fill_kernel() {
    int e = blockIdx.x * blockDim.x + threadIdx.x;
    if (e >= NE) return;
    int d = g_dsti[e];
    int pos = atomicAdd(&g_cnt[d], 1);
    g_col[pos] = g_srci[e];
}

// ---------------- prep: x16 = x * norm_s (fp16) -----------------------------
__global__ void __launch_bounds__(256) prepx_kernel(const float* __restrict__ in) {
    int t = blockIdx.x * 256 + threadIdx.x;
    int node = t >> 5;
    if (node >= NN) return;
    int c = (t & 31) * 4;
    float ns = g_norms[node];
    float4 v = *(const float4*)(in + (size_t)node * HID + c);
    __half2 h0 = __floats2half2_rn(v.x * ns, v.y * ns);
    __half2 h1 = __floats2half2_rn(v.z * ns, v.w * ns);
    uint2 u;
    u.x = *(unsigned*)&h0;
    u.y = *(unsigned*)&h1;
    *(uint2*)(g_x16 + (size_t)node * HID + c) = u;
}

// ---------------- SpMM layer1: warp per dst node, fp16 unweighted gather ----
__global__ void __launch_bounds__(256) spmm128_f16_kernel() {
    int t = blockIdx.x * 256 + threadIdx.x;
    int d = t >> 5;
    int lane = t & 31;
    if (d >= NN) return;
    int c = lane * 4;
    int beg = g_rowptr[d], end = g_rowptr[d + 1];
    float ax = 0.f, ay = 0.f, az = 0.f, aw = 0.f;
    int j = beg;
    for (; j + 3 < end; j += 4) {
        int s0 = g_col[j], s1 = g_col[j + 1], s2 = g_col[j + 2], s3 = g_col[j + 3];
        uint2 u0 = *(const uint2*)(g_x16 + (size_t)s0 * HID + c);
        uint2 u1 = *(const uint2*)(g_x16 + (size_t)s1 * HID + c);
        uint2 u2 = *(const uint2*)(g_x16 + (size_t)s2 * HID + c);
        uint2 u3 = *(const uint2*)(g_x16 + (size_t)s3 * HID + c);
        float2 a = __half22float2(*(__half2*)&u0.x), b = __half22float2(*(__half2*)&u0.y);
        ax += a.x; ay += a.y; az += b.x; aw += b.y;
        a = __half22float2(*(__half2*)&u1.x); b = __half22float2(*(__half2*)&u1.y);
        ax += a.x; ay += a.y; az += b.x; aw += b.y;
        a = __half22float2(*(__half2*)&u2.x); b = __half22float2(*(__half2*)&u2.y);
        ax += a.x; ay += a.y; az += b.x; aw += b.y;
        a = __half22float2(*(__half2*)&u3.x); b = __half22float2(*(__half2*)&u3.y);
        ax += a.x; ay += a.y; az += b.x; aw += b.y;
    }
    for (; j < end; j++) {
        int s = g_col[j];
        uint2 u = *(const uint2*)(g_x16 + (size_t)s * HID + c);
        float2 a = __half22float2(*(__half2*)&u.x), b = __half22float2(*(__half2*)&u.y);
        ax += a.x; ay += a.y; az += b.x; aw += b.y;
    }
    float nd = g_normd[d];
    float4 o = make_float4(ax * nd, ay * nd, az * nd, aw * nd);
    *(float4*)(g_m + (size_t)d * HID + c) = o;
}

// ---------------- SpMM layer2: fp32, affine1 + norms folded in-loop (R3) ----
__global__ void __launch_bounds__(256) spmm128_f32_kernel() {
    int t = blockIdx.x * 256 + threadIdx.x;
    int d = t >> 5;
    int lane = t & 31;
    if (d >= NN) return;
    int c = lane * 4;
    float4 sc = *(const float4*)(g_scale1 + c);
    float4 sh = *(const float4*)(g_shift1 + c);
    int beg = g_rowptr[d], end = g_rowptr[d + 1];
    float ax = 0.f, ay = 0.f, az = 0.f, aw = 0.f;
    int j = beg;
    for (; j + 3 < end; j += 4) {
        int s0 = g_col[j], s1 = g_col[j + 1], s2 = g_col[j + 2], s3 = g_col[j + 3];
        float w0 = g_norms[s0], w1 = g_norms[s1], w2 = g_norms[s2], w3 = g_norms[s3];
        float4 v0 = *(const float4*)(g_t + (size_t)s0 * HID + c);
        float4 v1 = *(const float4*)(g_t + (size_t)s1 * HID + c);
        float4 v2 = *(const float4*)(g_t + (size_t)s2 * HID + c);
        float4 v3 = *(const float4*)(g_t + (size_t)s3 * HID + c);
        v0 = affine4(v0, sc, sh); v1 = affine4(v1, sc, sh);
        v2 = affine4(v2, sc, sh); v3 = affine4(v3, sc, sh);
        ax += w0 * v0.x + w1 * v1.x + w2 * v2.x + w3 * v3.x;
        ay += w0 * v0.y + w1 * v1.y + w2 * v2.y + w3 * v3.y;
        az += w0 * v0.z + w1 * v1.z + w2 * v2.z + w3 * v3.z;
        aw += w0 * v0.w + w1 * v1.w + w2 * v2.w + w3 * v3.w;
    }
    for (; j < end; j++) {
        int s = g_col[j];
        float w = g_norms[s];
        float4 v = *(const float4*)(g_t + (size_t)s * HID + c);
        v = affine4(v, sc, sh);
        ax += w * v.x; ay += w * v.y; az += w * v.z; aw += w * v.w;
    }
    float nd = g_normd[d];
    float4 o = make_float4(ax * nd, ay * nd, az * nd, aw * nd);
    *(float4*)(g_m + (size_t)d * HID + c) = o;
}

// ---------------- SpMM 64-wide fp16 + bias + log_softmax (final layer) ------
__global__ void __launch_bounds__(256) spmm64_kernel(const float* __restrict__ b3,
                                                     float* __restrict__ out) {
    int t = blockIdx.x * 256 + threadIdx.x;
    int d = t >> 5;
    int lane = t & 31;
    if (d >= NN) return;
    int c = lane * 2;
    int beg = g_rowptr[d], end = g_rowptr[d + 1];
    float a0 = 0.f, a1 = 0.f;
    int j = beg;
    for (; j + 3 < end; j += 4) {
        int s0 = g_col[j], s1 = g_col[j + 1], s2 = g_col[j + 2], s3 = g_col[j + 3];
        float2 v0 = __half22float2(*(const __half2*)(g_z16 + (size_t)s0 * OUTF + c));
        float2 v1 = __half22float2(*(const __half2*)(g_z16 + (size_t)s1 * OUTF + c));
        float2 v2 = __half22float2(*(const __half2*)(g_z16 + (size_t)s2 * OUTF + c));
        float2 v3 = __half22float2(*(const __half2*)(g_z16 + (size_t)s3 * OUTF + c));
        a0 += v0.x + v1.x + v2.x + v3.x;
        a1 += v0.y + v1.y + v2.y + v3.y;
    }
    for (; j < end; j++) {
        int s = g_col[j];
        float2 v = __half22float2(*(const __half2*)(g_z16 + (size_t)s * OUTF + c));
        a0 += v.x; a1 += v.y;
    }
    float nd = g_normd[d];
    a0 = a0 * nd + b3[c];
    a1 = a1 * nd + b3[c + 1];
    float mx = fmaxf(a0, a1);
    #pragma unroll
    for (int off = 16; off > 0; off >>= 1)
        mx = fmaxf(mx, __shfl_xor_sync(0xffffffffu, mx, off));
    float e = expf(a0 - mx) + expf(a1 - mx);
    #pragma unroll
    for (int off = 16; off > 0; off >>= 1)
        e += __shfl_xor_sync(0xffffffffu, e, off);
    float l = logf(e);
    out[(size_t)d * OUTF + c]     = a0 - mx - l;
    out[(size_t)d * OUTF + c + 1] = a1 - mx - l;
}

// ---------------- GEMM ----------------
// NC==128 : g_t = relu(g_m @ W + bias) fp32; BN stats accumulated
// NC==64  : g_z16 = ((g_t*scale2+shift2)*norm_s) @ W  -> fp16
template<int NC, bool STATS>
__global__ void __launch_bounds__(256)
gemm_kernel(const float* __restrict__ W, const float* __restrict__ bias, int stats_off) {
    constexpr bool TRANS = (NC == 64);
    const float* __restrict__ A = TRANS ? g_t : g_m;
    constexpr int CJ = NC / 16;

    __shared__ float As[128][33];
    __shared__ float Bs[32][NC];

    int tid = threadIdx.x;
    int tx = tid & 15, ty = tid >> 4;
    int row0 = blockIdx.x * 128;

    float acc[8][CJ];
    #pragma unroll
    for (int i = 0; i < 8; i++)
        #pragma unroll
        for (int j = 0; j < CJ; j++) acc[i][j] = 0.f;

    for (int kk = 0; kk < 128; kk += 32) {
        #pragma unroll
        for (int l = 0; l < 4; l++) {
            int idx = tid + l * 256;
            int r = idx >> 3;
            int c4 = idx & 7;
            int grow = row0 + r;
            float4 v = make_float4(0, 0, 0, 0);
            if (grow < NN) v = *(const float4*)(A + (size_t)grow * 128 + kk + c4 * 4);
            if (TRANS) {
                int cb = kk + c4 * 4;
                float ns = (grow < NN) ? g_norms[grow] : 0.f;
                v.x = fmaf(v.x, g_scale2[cb + 0], g_shift2[cb + 0]) * ns;
                v.y = fmaf(v.y, g_scale2[cb + 1], g_shift2[cb + 1]) * ns;
                v.z = fmaf(v.z, g_scale2[cb + 2], g_shift2[cb + 2]) * ns;
                v.w = fmaf(v.w, g_scale2[cb + 3], g_shift2[cb + 3]) * ns;
            }
            As[r][c4 * 4 + 0] = v.x;
            As[r][c4 * 4 + 1] = v.y;
            As[r][c4 * 4 + 2] = v.z;
            As[r][c4 * 4 + 3] = v.w;
        }
        constexpr int BL = 32 * NC / (256 * 4);
        #pragma unroll
        for (int l = 0; l < BL; l++) {
            int idx = tid + l * 256;
            int k = idx / (NC / 4);
            int c4 = idx % (NC / 4);
            float4 v = *(const float4*)(W + (size_t)(kk + k) * NC + c4 * 4);
            *(float4*)(&Bs[k][c4 * 4]) = v;
        }
        __syncthreads();
        #pragma unroll
        for (int k = 0; k < 32; k++) {
            float a[8], b[CJ];
            #pragma unroll
            for (int i = 0; i < 8; i++) a[i] = As[ty * 8 + i][k];
            #pragma unroll
            for (int j = 0; j < CJ; j += 4) {
                float4 bv = *(const float4*)(&Bs[k][tx * CJ + j]);
                b[j] = bv.x; b[j + 1] = bv.y; b[j + 2] = bv.z; b[j + 3] = bv.w;
            }
            #pragma unroll
            for (int i = 0; i < 8; i++)
                #pragma unroll
                for (int j = 0; j < CJ; j++)
                    acc[i][j] = fmaf(a[i], b[j], acc[i][j]);
        }
        __syncthreads();
    }

    float bb[CJ];
    if (STATS) {
        #pragma unroll
        for (int j = 0; j < CJ; j++) bb[j] = bias[tx * CJ + j];
    }
    float psum[CJ], psq[CJ];
    #pragma unroll
    for (int j = 0; j < CJ; j++) { psum[j] = 0.f; psq[j] = 0.f; }

    #pragma unroll
    for (int i = 0; i < 8; i++) {
        int grow = row0 + ty * 8 + i;
        if (grow < NN) {
            float vout[CJ];
            #pragma unroll
            for (int j = 0; j < CJ; j++) {
                float v = acc[i][j];
                if (STATS) {
                    v += bb[j];
                    v = fmaxf(v, 0.f);
                    psum[j] += v;
                    psq[j] += v * v;
                }
                vout[j] = v;
            }
            if (TRANS) {
                __half2 h0 = __floats2half2_rn(vout[0], vout[1]);
                __half2 h1 = __floats2half2_rn(vout[2], vout[3]);
                uint2 u;
                u.x = *(unsigned*)&h0;
                u.y = *(unsigned*)&h1;
                *(uint2*)(g_z16 + (size_t)grow * NC + tx * CJ) = u;
            } else {
                float* cp = g_t + (size_t)grow * NC + tx * CJ;
                #pragma unroll
                for (int j = 0; j < CJ; j += 4)
                    *(float4*)(cp + j) = make_float4(vout[j], vout[j + 1], vout[j + 2], vout[j + 3]);
            }
        }
    }

    if (STATS) {
        __syncthreads();
        float* p = &As[0][0];
        float* ssum = p;
        float* ssq = p + 16 * NC;
        #pragma unroll
        for (int j = 0; j < CJ; j++) {
            ssum[ty * NC + tx * CJ + j] = psum[j];
            ssq [ty * NC + tx * CJ + j] = psq[j];
        }
        __syncthreads();
        if (tid < NC) {
            float s = 0.f, q = 0.f;
            #pragma unroll
            for (int r = 0; r < 16; r++) { s += ssum[r * NC + tid]; q += ssq[r * NC + tid]; }
            atomicAdd(&g_stats[stats_off + tid], s);
            atomicAdd(&g_stats[stats_off + NC + tid], q);
        }
    }
}

// ---------------- BN finalize ----------------
__global__ void bnfin_kernel(const float* __restrict__ gamma, const float* __restrict__ beta,
                             int stats_off, int which) {
    int c = threadIdx.x;
    if (c < HID) {
        float inv_n = 1.0f / (float)NN;
        float mean = g_stats[stats_off + c] * inv_n;
        float var = g_stats[stats_off + HID + c] * inv_n - mean * mean;
        float sc = gamma[c] * rsqrtf(var + 1e-5f);
        float sh = beta[c] - mean * sc;
        if (which == 1) { g_scale1[c] = sc; g_shift1[c] = sh; }
        else            { g_scale2[c] = sc; g_shift2[c] = sh; }
    }
}

// ---------------- launch ----------------
extern "C" void kernel_launch(void* const* d_in, const int* in_sizes, int n_in,
                              void* d_out, int out_size) {
    const float* x      = (const float*)d_in[0];
    const void*  src    = d_in[1];
    const void*  dst    = d_in[2];
    const float* W1     = (const float*)d_in[3];
    const float* b1     = (const float*)d_in[4];
    const float* W2     = (const float*)d_in[5];
    const float* b2     = (const float*)d_in[6];
    const float* W3     = (const float*)d_in[7];
    const float* b3     = (const float*)d_in[8];
    const float* gamma1 = (const float*)d_in[9];
    const float* beta1  = (const float*)d_in[10];
    const float* gamma2 = (const float*)d_in[11];
    const float* beta2  = (const float*)d_in[12];
    float* out = (float*)d_out;

    const int NB  = (NN + 255) / 256;       // 391
    const int EB  = (NE + 255) / 256;       // 12500
    const int WB  = (NN * 32 + 255) / 256;  // 12500 (warp per node)
    const int GB  = (NN + 127) / 128;       // 782

    init_kernel<<<NB, 256>>>(src);
    degree_kernel<<<EB, 256>>>(src, dst);
    scan_kernel<<<SCAN_NB, 256>>>();
    fill_kernel<<<EB, 256>>>();

    // layer 1: x16 = x * norm_s (fp16), fp16 gather-sum, GEMM+relu+stats
    prepx_kernel<<<WB, 256>>>(x);
    spmm128_f16_kernel<<<WB, 256>>>();
    gemm_kernel<128, true><<<GB, 256>>>(W1, b1, 0);
    bnfin_kernel<<<1, 128>>>(gamma1, beta1, 0, 1);

    // layer 2: pure fp32 path (R3): affine1 + norms inside the gather
    spmm128_f32_kernel<<<WB, 256>>>();
    gemm_kernel<128, true><<<GB, 256>>>(W2, b2, 256);
    bnfin_kernel<<<1, 128>>>(gamma2, beta2, 256, 2);

    // layer 3: GEMM (affine2 + norm_s folded, fp16 out), fp16 gather + softmax
    gemm_kernel<64, false><<<GB, 256>>>(W3, nullptr, 0);
    spmm64_kernel<<<WB, 256>>>(b3, out);
}

// round 6
// speedup vs baseline: 1.3363x; 1.0573x over previous
#include <cuda_runtime.h>
#include <cuda_fp16.h>
#include <cstdint>

#define NN 100000
#define NE 3200000
#define HID 128
#define OUTF 64
#define SCAN_NB 391   // ceil(NN/256)

// ---------------- device scratch (static, no allocation) ----------------
// NOTE: these symbols are referenced ONLY inside device code (never passed
// from host) — passing a __device__ symbol by value from host was R4's bug.
__device__ int    g_is64;
__device__ int    g_degout[NN];
__device__ int    g_degin[NN];
__device__ float  g_norms[NN];
__device__ float  g_normd[NN];
__device__ int    g_rowptr[NN + 1];
__device__ int    g_cnt[NN];
__device__ int    g_srci[NE];
__device__ int    g_dsti[NE];
__device__ int    g_col[NE];
__device__ unsigned long long g_scanstate[SCAN_NB];
__device__ float  g_m[(size_t)NN * HID];    // aggregation output (fp32)
__device__ float  g_t[(size_t)NN * HID];    // relu output (fp32)
__device__ __half g_x16[(size_t)NN * HID];  // x * norm_s (fp16)
__device__ __half g_t16[(size_t)NN * HID];  // affine1(t) * norm_s (fp16)
__device__ __half g_z16[(size_t)NN * OUTF]; // layer-3 pre-aggregation (fp16)
__device__ float  g_stats[512];
__device__ float  g_scale1[HID], g_shift1[HID];
__device__ float  g_scale2[HID], g_shift2[HID];

// ---------------- init: zero counters + dtype detect ----------------
__global__ void init_kernel(const void* src) {
    int i = blockIdx.x * blockDim.x + threadIdx.x;
    if (i < NN) { g_degout[i] = 0; g_degin[i] = 0; }
    if (i < 512) g_stats[i] = 0.f;
    if (i < SCAN_NB) g_scanstate[i] = 0ull;
    if (i == 0) {
        const long long* p = (const long long*)src;
        int ok = 1;
        #pragma unroll 1
        for (int k = 0; k < 128; k++) {
            long long v = p[k];
            if (v < 0 || v >= NN) { ok = 0; break; }
        }
        g_is64 = ok;
    }
}

// ---------------- degrees + int32 conversion ----------------
__global__ void degree_kernel(const void* src, const void* dst) {
    int e = blockIdx.x * blockDim.x + threadIdx.x;
    if (e >= NE) return;
    int is64 = g_is64;
    int s = is64 ? (int)((const long long*)src)[e] : ((const int*)src)[e];
    int d = is64 ? (int)((const long long*)dst)[e] : ((const int*)dst)[e];
    g_srci[e] = s;
    g_dsti[e] = d;
    atomicAdd(&g_degout[s], 1);
    atomicAdd(&g_degin[d], 1);
}

// ---------------- single-pass scan (decoupled lookback) + norms ----------------
__global__ void __launch_bounds__(256) scan_kernel() {
    int bid = blockIdx.x;
    int t = threadIdx.x;
    int lane = t & 31, wid = t >> 5;
    int i = bid * 256 + t;
    int v = (i < NN) ? g_degin[i] : 0;

    int x = v;
    #pragma unroll
    for (int off = 1; off < 32; off <<= 1) {
        int y = __shfl_up_sync(0xffffffffu, x, off);
        if (lane >= off) x += y;
    }
    __shared__ int wsum[8];
    if (lane == 31) wsum[wid] = x;
    __syncthreads();
    if (wid == 0 && lane < 8) {
        int w = wsum[lane];
        #pragma unroll
        for (int off = 1; off < 8; off <<= 1) {
            int y = __shfl_up_sync(0xffu, w, off);
            if (lane >= off) w += y;
        }
        wsum[lane] = w;
    }
    __syncthreads();
    int incl = x + (wid > 0 ? wsum[wid - 1] : 0);
    int bsum = wsum[7];

    __shared__ int s_excl;
    if (t == 0) {
        if (bid == 0) {
            atomicExch(&g_scanstate[0], (2ull << 32) | (unsigned long long)(unsigned)bsum);
            s_excl = 0;
        } else {
            atomicExch(&g_scanstate[bid], (1ull << 32) | (unsigned long long)(unsigned)bsum);
            long long running = 0;
            int j = bid - 1;
            while (true) {
                unsigned long long st = atomicAdd(&g_scanstate[j], 0ull);
                unsigned f = (unsigned)(st >> 32);
                if (f == 0u) continue;
                running += (long long)(unsigned)st;
                if (f == 2u) break;
                j--;
            }
            s_excl = (int)running;
            atomicExch(&g_scanstate[bid],
                       (2ull << 32) | (unsigned long long)(unsigned)(running + bsum));
        }
    }
    __syncthreads();
    int base = s_excl;
    if (i < NN) {
        int r = base + incl - v;
        g_rowptr[i] = r;
        g_cnt[i] = r;
        int dout = g_degout[i]; if (dout < 1) dout = 1;
        int din = v; if (din < 1) din = 1;
        g_norms[i] = rsqrtf((float)dout);
        g_normd[i] = rsqrtf((float)din);
        if (i == NN - 1) g_rowptr[NN] = r + v;
    }
}

__global__ void fill_kernel() {
    int e = blockIdx.x * blockDim.x + threadIdx.x;
    if (e >= NE) return;
    int d = g_dsti[e];
    int pos = atomicAdd(&g_cnt[d], 1);
    g_col[pos] = g_srci[e];
}

// ---------------- prep: x16 = x * norm_s (fp16); external input ------------
__global__ void __launch_bounds__(256) prepx_kernel(const float* __restrict__ in) {
    int t = blockIdx.x * 256 + threadIdx.x;
    int node = t >> 5;
    if (node >= NN) return;
    int c = (t & 31) * 4;
    float ns = g_norms[node];
    float4 v = *(const float4*)(in + (size_t)node * HID + c);
    __half2 h0 = __floats2half2_rn(v.x * ns, v.y * ns);
    __half2 h1 = __floats2half2_rn(v.z * ns, v.w * ns);
    uint2 u;
    u.x = *(unsigned*)&h0;
    u.y = *(unsigned*)&h1;
    *(uint2*)(g_x16 + (size_t)node * HID + c) = u;
}

// ---------------- prep: t16 = affine1(g_t) * norm_s (fp16); all globals -----
__global__ void __launch_bounds__(256) prept_kernel() {
    int t = blockIdx.x * 256 + threadIdx.x;
    int node = t >> 5;
    if (node >= NN) return;
    int c = (t & 31) * 4;
    float ns = g_norms[node];
    float4 v = *(const float4*)(g_t + (size_t)node * HID + c);
    v.x = fmaf(v.x, g_scale1[c + 0], g_shift1[c + 0]) * ns;
    v.y = fmaf(v.y, g_scale1[c + 1], g_shift1[c + 1]) * ns;
    v.z = fmaf(v.z, g_scale1[c + 2], g_shift1[c + 2]) * ns;
    v.w = fmaf(v.w, g_scale1[c + 3], g_shift1[c + 3]) * ns;
    __half2 h0 = __floats2half2_rn(v.x, v.y);
    __half2 h1 = __floats2half2_rn(v.z, v.w);
    uint2 u;
    u.x = *(unsigned*)&h0;
    u.y = *(unsigned*)&h1;
    *(uint2*)(g_t16 + (size_t)node * HID + c) = u;
}

// ---------------- SpMM: warp per dst node, fp16 unweighted gather -----------
// WHICH: 0 -> g_x16 (layer 1), 1 -> g_t16 (layer 2). Buffer chosen in device code.
template<int WHICH>
__global__ void __launch_bounds__(256) spmm128_f16_kernel() {
    int t = blockIdx.x * 256 + threadIdx.x;
    int d = t >> 5;
    int lane = t & 31;
    if (d >= NN) return;
    const __half* __restrict__ h = (WHICH == 0) ? g_x16 : g_t16;
    int c = lane * 4;
    int beg = g_rowptr[d], end = g_rowptr[d + 1];
    float ax = 0.f, ay = 0.f, az = 0.f, aw = 0.f;
    int j = beg;
    for (; j + 3 < end; j += 4) {
        int s0 = g_col[j], s1 = g_col[j + 1], s2 = g_col[j + 2], s3 = g_col[j + 3];
        uint2 u0 = *(const uint2*)(h + (size_t)s0 * HID + c);
        uint2 u1 = *(const uint2*)(h + (size_t)s1 * HID + c);
        uint2 u2 = *(const uint2*)(h + (size_t)s2 * HID + c);
        uint2 u3 = *(const uint2*)(h + (size_t)s3 * HID + c);
        float2 a = __half22float2(*(__half2*)&u0.x), b = __half22float2(*(__half2*)&u0.y);
        ax += a.x; ay += a.y; az += b.x; aw += b.y;
        a = __half22float2(*(__half2*)&u1.x); b = __half22float2(*(__half2*)&u1.y);
        ax += a.x; ay += a.y; az += b.x; aw += b.y;
        a = __half22float2(*(__half2*)&u2.x); b = __half22float2(*(__half2*)&u2.y);
        ax += a.x; ay += a.y; az += b.x; aw += b.y;
        a = __half22float2(*(__half2*)&u3.x); b = __half22float2(*(__half2*)&u3.y);
        ax += a.x; ay += a.y; az += b.x; aw += b.y;
    }
    for (; j < end; j++) {
        int s = g_col[j];
        uint2 u = *(const uint2*)(h + (size_t)s * HID + c);
        float2 a = __half22float2(*(__half2*)&u.x), b = __half22float2(*(__half2*)&u.y);
        ax += a.x; ay += a.y; az += b.x; aw += b.y;
    }
    float nd = g_normd[d];
    float4 o = make_float4(ax * nd, ay * nd, az * nd, aw * nd);
    *(float4*)(g_m + (size_t)d * HID + c) = o;
}

// ---------------- SpMM 64-wide fp16 + bias + log_softmax (final layer) ------
__global__ void __launch_bounds__(256) spmm64_kernel(const float* __restrict__ b3,
                                                     float* __restrict__ out) {
    int t = blockIdx.x * 256 + threadIdx.x;
    int d = t >> 5;
    int lane = t & 31;
    if (d >= NN) return;
    int c = lane * 2;
    int beg = g_rowptr[d], end = g_rowptr[d + 1];
    float a0 = 0.f, a1 = 0.f;
    int j = beg;
    for (; j + 3 < end; j += 4) {
        int s0 = g_col[j], s1 = g_col[j + 1], s2 = g_col[j + 2], s3 = g_col[j + 3];
        float2 v0 = __half22float2(*(const __half2*)(g_z16 + (size_t)s0 * OUTF + c));
        float2 v1 = __half22float2(*(const __half2*)(g_z16 + (size_t)s1 * OUTF + c));
        float2 v2 = __half22float2(*(const __half2*)(g_z16 + (size_t)s2 * OUTF + c));
        float2 v3 = __half22float2(*(const __half2*)(g_z16 + (size_t)s3 * OUTF + c));
        a0 += v0.x + v1.x + v2.x + v3.x;
        a1 += v0.y + v1.y + v2.y + v3.y;
    }
    for (; j < end; j++) {
        int s = g_col[j];
        float2 v = __half22float2(*(const __half2*)(g_z16 + (size_t)s * OUTF + c));
        a0 += v.x; a1 += v.y;
    }
    float nd = g_normd[d];
    a0 = a0 * nd + b3[c];
    a1 = a1 * nd + b3[c + 1];
    float mx = fmaxf(a0, a1);
    #pragma unroll
    for (int off = 16; off > 0; off >>= 1)
        mx = fmaxf(mx, __shfl_xor_sync(0xffffffffu, mx, off));
    float e = expf(a0 - mx) + expf(a1 - mx);
    #pragma unroll
    for (int off = 16; off > 0; off >>= 1)
        e += __shfl_xor_sync(0xffffffffu, e, off);
    float l = logf(e);
    out[(size_t)d * OUTF + c]     = a0 - mx - l;
    out[(size_t)d * OUTF + c + 1] = a1 - mx - l;
}

// ---------------- GEMM ----------------
// NC==128 : g_t = relu(g_m @ W + bias) fp32; BN stats accumulated
// NC==64  : g_z16 = ((g_t*scale2+shift2)*norm_s) @ W  -> fp16
template<int NC, bool STATS>
__global__ void __launch_bounds__(256)
gemm_kernel(const float* __restrict__ W, const float* __restrict__ bias, int stats_off) {
    constexpr bool TRANS = (NC == 64);
    const float* __restrict__ A = TRANS ? g_t : g_m;
    constexpr int CJ = NC / 16;

    __shared__ float As[128][33];
    __shared__ float Bs[32][NC];

    int tid = threadIdx.x;
    int tx = tid & 15, ty = tid >> 4;
    int row0 = blockIdx.x * 128;

    float acc[8][CJ];
    #pragma unroll
    for (int i = 0; i < 8; i++)
        #pragma unroll
        for (int j = 0; j < CJ; j++) acc[i][j] = 0.f;

    for (int kk = 0; kk < 128; kk += 32) {
        #pragma unroll
        for (int l = 0; l < 4; l++) {
            int idx = tid + l * 256;
            int r = idx >> 3;
            int c4 = idx & 7;
            int grow = row0 + r;
            float4 v = make_float4(0, 0, 0, 0);
            if (grow < NN) v = *(const float4*)(A + (size_t)grow * 128 + kk + c4 * 4);
            if (TRANS) {
                int cb = kk + c4 * 4;
                float ns = (grow < NN) ? g_norms[grow] : 0.f;
                v.x = fmaf(v.x, g_scale2[cb + 0], g_shift2[cb + 0]) * ns;
                v.y = fmaf(v.y, g_scale2[cb + 1], g_shift2[cb + 1]) * ns;
                v.z = fmaf(v.z, g_scale2[cb + 2], g_shift2[cb + 2]) * ns;
                v.w = fmaf(v.w, g_scale2[cb + 3], g_shift2[cb + 3]) * ns;
            }
            As[r][c4 * 4 + 0] = v.x;
            As[r][c4 * 4 + 1] = v.y;
            As[r][c4 * 4 + 2] = v.z;
            As[r][c4 * 4 + 3] = v.w;
        }
        constexpr int BL = 32 * NC / (256 * 4);
        #pragma unroll
        for (int l = 0; l < BL; l++) {
            int idx = tid + l * 256;
            int k = idx / (NC / 4);
            int c4 = idx % (NC / 4);
            float4 v = *(const float4*)(W + (size_t)(kk + k) * NC + c4 * 4);
            *(float4*)(&Bs[k][c4 * 4]) = v;
        }
        __syncthreads();
        #pragma unroll
        for (int k = 0; k < 32; k++) {
            float a[8], b[CJ];
            #pragma unroll
            for (int i = 0; i < 8; i++) a[i] = As[ty * 8 + i][k];
            #pragma unroll
            for (int j = 0; j < CJ; j += 4) {
                float4 bv = *(const float4*)(&Bs[k][tx * CJ + j]);
                b[j] = bv.x; b[j + 1] = bv.y; b[j + 2] = bv.z; b[j + 3] = bv.w;
            }
            #pragma unroll
            for (int i = 0; i < 8; i++)
                #pragma unroll
                for (int j = 0; j < CJ; j++)
                    acc[i][j] = fmaf(a[i], b[j], acc[i][j]);
        }
        __syncthreads();
    }

    float bb[CJ];
    if (STATS) {
        #pragma unroll
        for (int j = 0; j < CJ; j++) bb[j] = bias[tx * CJ + j];
    }
    float psum[CJ], psq[CJ];
    #pragma unroll
    for (int j = 0; j < CJ; j++) { psum[j] = 0.f; psq[j] = 0.f; }

    #pragma unroll
    for (int i = 0; i < 8; i++) {
        int grow = row0 + ty * 8 + i;
        if (grow < NN) {
            float vout[CJ];
            #pragma unroll
            for (int j = 0; j < CJ; j++) {
                float v = acc[i][j];
                if (STATS) {
                    v += bb[j];
                    v = fmaxf(v, 0.f);
                    psum[j] += v;
                    psq[j] += v * v;
                }
                vout[j] = v;
            }
            if (TRANS) {
                __half2 h0 = __floats2half2_rn(vout[0], vout[1]);
                __half2 h1 = __floats2half2_rn(vout[2], vout[3]);
                uint2 u;
                u.x = *(unsigned*)&h0;
                u.y = *(unsigned*)&h1;
                *(uint2*)(g_z16 + (size_t)grow * NC + tx * CJ) = u;
            } else {
                float* cp = g_t + (size_t)grow * NC + tx * CJ;
                #pragma unroll
                for (int j = 0; j < CJ; j += 4)
                    *(float4*)(cp + j) = make_float4(vout[j], vout[j + 1], vout[j + 2], vout[j + 3]);
            }
        }
    }

    if (STATS) {
        __syncthreads();
        float* p = &As[0][0];
        float* ssum = p;
        float* ssq = p + 16 * NC;
        #pragma unroll
        for (int j = 0; j < CJ; j++) {
            ssum[ty * NC + tx * CJ + j] = psum[j];
            ssq [ty * NC + tx * CJ + j] = psq[j];
        }
        __syncthreads();
        if (tid < NC) {
            float s = 0.f, q = 0.f;
            #pragma unroll
            for (int r = 0; r < 16; r++) { s += ssum[r * NC + tid]; q += ssq[r * NC + tid]; }
            atomicAdd(&g_stats[stats_off + tid], s);
            atomicAdd(&g_stats[stats_off + NC + tid], q);
        }
    }
}

// ---------------- BN finalize ----------------
__global__ void bnfin_kernel(const float* __restrict__ gamma, const float* __restrict__ beta,
                             int stats_off, int which) {
    int c = threadIdx.x;
    if (c < HID) {
        float inv_n = 1.0f / (float)NN;
        float mean = g_stats[stats_off + c] * inv_n;
        float var = g_stats[stats_off + HID + c] * inv_n - mean * mean;
        float sc = gamma[c] * rsqrtf(var + 1e-5f);
        float sh = beta[c] - mean * sc;
        if (which == 1) { g_scale1[c] = sc; g_shift1[c] = sh; }
        else            { g_scale2[c] = sc; g_shift2[c] = sh; }
    }
}

// ---------------- launch ----------------
extern "C" void kernel_launch(void* const* d_in, const int* in_sizes, int n_in,
                              void* d_out, int out_size) {
    const float* x      = (const float*)d_in[0];
    const void*  src    = d_in[1];
    const void*  dst    = d_in[2];
    const float* W1     = (const float*)d_in[3];
    const float* b1     = (const float*)d_in[4];
    const float* W2     = (const float*)d_in[5];
    const float* b2     = (const float*)d_in[6];
    const float* W3     = (const float*)d_in[7];
    const float* b3     = (const float*)d_in[8];
    const float* gamma1 = (const float*)d_in[9];
    const float* beta1  = (const float*)d_in[10];
    const float* gamma2 = (const float*)d_in[11];
    const float* beta2  = (const float*)d_in[12];
    float* out = (float*)d_out;

    const int NB  = (NN + 255) / 256;       // 391
    const int EB  = (NE + 255) / 256;       // 12500
    const int WB  = (NN * 32 + 255) / 256;  // 12500 (warp per node)
    const int GB  = (NN + 127) / 128;       // 782

    init_kernel<<<NB, 256>>>(src);
    degree_kernel<<<EB, 256>>>(src, dst);
    scan_kernel<<<SCAN_NB, 256>>>();
    fill_kernel<<<EB, 256>>>();

    // layer 1: x16 = x * norm_s (fp16), fp16 gather-sum, GEMM+relu+stats
    prepx_kernel<<<WB, 256>>>(x);
    spmm128_f16_kernel<0><<<WB, 256>>>();
    gemm_kernel<128, true><<<GB, 256>>>(W1, b1, 0);
    bnfin_kernel<<<1, 128>>>(gamma1, beta1, 0, 1);

    // layer 2: t16 = affine1(t) * norm_s (fp16), fp16 gather-sum
    prept_kernel<<<WB, 256>>>();
    spmm128_f16_kernel<1><<<WB, 256>>>();
    gemm_kernel<128, true><<<GB, 256>>>(W2, b2, 256);
    bnfin_kernel<<<1, 128>>>(gamma2, beta2, 256, 2);

    // layer 3: GEMM (affine2 + norm_s folded, fp16 out), fp16 gather + softmax
    gemm_kernel<64, false><<<GB, 256>>>(W3, nullptr, 0);
    spmm64_kernel<<<WB, 256>>>(b3, out);
}

// round 7
// speedup vs baseline: 1.3664x; 1.0225x over previous
#include <cuda_runtime.h>
#include <cuda_fp16.h>
#include <mma.h>
#include <cstdint>

using namespace nvcuda;

#define NN 100000
#define NNP 100096          // 782 * 128, padded for TC GEMM tiles
#define NE 3200000
#define HID 128
#define OUTF 64
#define SCAN_NB 391         // ceil(NN/256)

// ---------------- device scratch (static, no allocation) ----------------
// NOTE: symbols referenced ONLY inside device code (never passed from host).
__device__ int    g_is64;
__device__ int    g_degout[NN];
__device__ int    g_degin[NN];
__device__ float  g_norms[NN];
__device__ float  g_normd[NN];
__device__ int    g_rowptr[NN + 1];
__device__ int    g_cnt[NN];
__device__ int    g_srci[NE];
__device__ int    g_dsti[NE];
__device__ int    g_col[NE];
__device__ unsigned long long g_scanstate[SCAN_NB];
__device__ __half g_x16[(size_t)NN * HID];    // x * norm_s (layer-1 gather src)
__device__ __half g_t16[(size_t)NN * HID];    // affine1(t) * norm_s (layer-2 gather src)
__device__ __half g_a16[(size_t)NNP * HID];   // spmm output = GEMM1/2 A (padded rows = 0)
__device__ __half g_t16raw[(size_t)NN * HID]; // relu(gemm) output, pre-affine
__device__ __half g_a316[(size_t)NNP * HID];  // affine2(t16raw) * norm_s = GEMM3 A
__device__ __half g_z16[(size_t)NN * OUTF];   // layer-3 pre-aggregation
__device__ __half g_w16[HID * HID];           // current weight, fp16
__device__ float  g_stats[512];
__device__ float  g_scale1[HID], g_shift1[HID];
__device__ float  g_scale2[HID], g_shift2[HID];

// ---------------- init: zero counters + dtype detect ----------------
__global__ void init_kernel(const void* src) {
    int i = blockIdx.x * blockDim.x + threadIdx.x;
    if (i < NN) { g_degout[i] = 0; g_degin[i] = 0; }
    if (i < 512) g_stats[i] = 0.f;
    if (i < SCAN_NB) g_scanstate[i] = 0ull;
    if (i == 0) {
        const long long* p = (const long long*)src;
        int ok = 1;
        #pragma unroll 1
        for (int k = 0; k < 128; k++) {
            long long v = p[k];
            if (v < 0 || v >= NN) { ok = 0; break; }
        }
        g_is64 = ok;
    }
}

// ---------------- degrees + int32 conversion ----------------
__global__ void degree_kernel(const void* src, const void* dst) {
    int e = blockIdx.x * blockDim.x + threadIdx.x;
    if (e >= NE) return;
    int is64 = g_is64;
    int s = is64 ? (int)((const long long*)src)[e] : ((const int*)src)[e];
    int d = is64 ? (int)((const long long*)dst)[e] : ((const int*)dst)[e];
    g_srci[e] = s;
    g_dsti[e] = d;
    atomicAdd(&g_degout[s], 1);
    atomicAdd(&g_degin[d], 1);
}

// ---------------- single-pass scan (decoupled lookback) + norms -------------
__global__ void __launch_bounds__(256) scan_kernel() {
    int bid = blockIdx.x;
    int t = threadIdx.x;
    int lane = t & 31, wid = t >> 5;
    int i = bid * 256 + t;
    int v = (i < NN) ? g_degin[i] : 0;

    int x = v;
    #pragma unroll
    for (int off = 1; off < 32; off <<= 1) {
        int y = __shfl_up_sync(0xffffffffu, x, off);
        if (lane >= off) x += y;
    }
    __shared__ int wsum[8];
    if (lane == 31) wsum[wid] = x;
    __syncthreads();
    if (wid == 0 && lane < 8) {
        int w = wsum[lane];
        #pragma unroll
        for (int off = 1; off < 8; off <<= 1) {
            int y = __shfl_up_sync(0xffu, w, off);
            if (lane >= off) w += y;
        }
        wsum[lane] = w;
    }
    __syncthreads();
    int incl = x + (wid > 0 ? wsum[wid - 1] : 0);
    int bsum = wsum[7];

    __shared__ int s_excl;
    if (t == 0) {
        if (bid == 0) {
            atomicExch(&g_scanstate[0], (2ull << 32) | (unsigned long long)(unsigned)bsum);
            s_excl = 0;
        } else {
            atomicExch(&g_scanstate[bid], (1ull << 32) | (unsigned long long)(unsigned)bsum);
            long long running = 0;
            int j = bid - 1;
            while (true) {
                unsigned long long st = atomicAdd(&g_scanstate[j], 0ull);
                unsigned f = (unsigned)(st >> 32);
                if (f == 0u) continue;
                running += (long long)(unsigned)st;
                if (f == 2u) break;
                j--;
            }
            s_excl = (int)running;
            atomicExch(&g_scanstate[bid],
                       (2ull << 32) | (unsigned long long)(unsigned)(running + bsum));
        }
    }
    __syncthreads();
    int base = s_excl;
    if (i < NN) {
        int r = base + incl - v;
        g_rowptr[i] = r;
        g_cnt[i] = r;
        int dout = g_degout[i]; if (dout < 1) dout = 1;
        int din = v; if (din < 1) din = 1;
        g_norms[i] = rsqrtf((float)dout);
        g_normd[i] = rsqrtf((float)din);
        if (i == NN - 1) g_rowptr[NN] = r + v;
    }
}

__global__ void fill_kernel() {
    int e = blockIdx.x * blockDim.x + threadIdx.x;
    if (e >= NE) return;
    int d = g_dsti[e];
    int pos = atomicAdd(&g_cnt[d], 1);
    g_col[pos] = g_srci[e];
}

// ---------------- prep: x16 = x * norm_s (fp16); external input -------------
__global__ void __launch_bounds__(256) prepx_kernel(const float* __restrict__ in) {
    int t = blockIdx.x * 256 + threadIdx.x;
    int node = t >> 5;
    if (node >= NN) return;
    int c = (t & 31) * 4;
    float ns = g_norms[node];
    float4 v = *(const float4*)(in + (size_t)node * HID + c);
    __half2 h0 = __floats2half2_rn(v.x * ns, v.y * ns);
    __half2 h1 = __floats2half2_rn(v.z * ns, v.w * ns);
    uint2 u;
    u.x = *(unsigned*)&h0;
    u.y = *(unsigned*)&h1;
    *(uint2*)(g_x16 + (size_t)node * HID + c) = u;
}

// ---------------- prep from t16raw: affine * norm_s -> fp16 -----------------
// WHICH 1: out g_t16, scale1/shift1 (layer-2 gather operand)
// WHICH 2: out g_a316, scale2/shift2 (layer-3 GEMM A)
template<int WHICH>
__global__ void __launch_bounds__(256) prept_kernel() {
    int t = blockIdx.x * 256 + threadIdx.x;
    int node = t >> 5;
    if (node >= NN) return;
    int c = (t & 31) * 4;
    const float* sc = (WHICH == 1) ? g_scale1 : g_scale2;
    const float* sh = (WHICH == 1) ? g_shift1 : g_shift2;
    __half* out = (WHICH == 1) ? g_t16 : g_a316;
    float ns = g_norms[node];
    uint2 u = *(const uint2*)(g_t16raw + (size_t)node * HID + c);
    float2 p0 = __half22float2(*(__half2*)&u.x);
    float2 p1 = __half22float2(*(__half2*)&u.y);
    float vx = fmaf(p0.x, sc[c + 0], sh[c + 0]) * ns;
    float vy = fmaf(p0.y, sc[c + 1], sh[c + 1]) * ns;
    float vz = fmaf(p1.x, sc[c + 2], sh[c + 2]) * ns;
    float vw = fmaf(p1.y, sc[c + 3], sh[c + 3]) * ns;
    __half2 h0 = __floats2half2_rn(vx, vy);
    __half2 h1 = __floats2half2_rn(vz, vw);
    uint2 o;
    o.x = *(unsigned*)&h0;
    o.y = *(unsigned*)&h1;
    *(uint2*)(out + (size_t)node * HID + c) = o;
}

// ---------------- weight fp32 -> fp16 ----------------
__global__ void convw_kernel(const float* __restrict__ W, int n) {
    int i = blockIdx.x * blockDim.x + threadIdx.x;
    if (i < n) g_w16[i] = __float2half_rn(W[i]);
}

// ---------------- SpMM: warp per dst node, fp16 unweighted gather -----------
// WHICH: 0 -> g_x16, 1 -> g_t16. Output: g_a16 (fp16).
template<int WHICH>
__global__ void __launch_bounds__(256) spmm128_f16_kernel() {
    int t = blockIdx.x * 256 + threadIdx.x;
    int d = t >> 5;
    int lane = t & 31;
    if (d >= NN) return;
    const __half* __restrict__ h = (WHICH == 0) ? g_x16 : g_t16;
    int c = lane * 4;
    int beg = g_rowptr[d], end = g_rowptr[d + 1];
    float ax = 0.f, ay = 0.f, az = 0.f, aw = 0.f;
    int j = beg;
    for (; j + 3 < end; j += 4) {
        int s0 = g_col[j], s1 = g_col[j + 1], s2 = g_col[j + 2], s3 = g_col[j + 3];
        uint2 u0 = *(const uint2*)(h + (size_t)s0 * HID + c);
        uint2 u1 = *(const uint2*)(h + (size_t)s1 * HID + c);
        uint2 u2 = *(const uint2*)(h + (size_t)s2 * HID + c);
        uint2 u3 = *(const uint2*)(h + (size_t)s3 * HID + c);
        float2 a = __half22float2(*(__half2*)&u0.x), b = __half22float2(*(__half2*)&u0.y);
        ax += a.x; ay += a.y; az += b.x; aw += b.y;
        a = __half22float2(*(__half2*)&u1.x); b = __half22float2(*(__half2*)&u1.y);
        ax += a.x; ay += a.y; az += b.x; aw += b.y;
        a = __half22float2(*(__half2*)&u2.x); b = __half22float2(*(__half2*)&u2.y);
        ax += a.x; ay += a.y; az += b.x; aw += b.y;
        a = __half22float2(*(__half2*)&u3.x); b = __half22float2(*(__half2*)&u3.y);
        ax += a.x; ay += a.y; az += b.x; aw += b.y;
    }
    for (; j < end; j++) {
        int s = g_col[j];
        uint2 u = *(const uint2*)(h + (size_t)s * HID + c);
        float2 a = __half22float2(*(__half2*)&u.x), b = __half22float2(*(__half2*)&u.y);
        ax += a.x; ay += a.y; az += b.x; aw += b.y;
    }
    float nd = g_normd[d];
    __half2 h0 = __floats2half2_rn(ax * nd, ay * nd);
    __half2 h1 = __floats2half2_rn(az * nd, aw * nd);
    uint2 o;
    o.x = *(unsigned*)&h0;
    o.y = *(unsigned*)&h1;
    *(uint2*)(g_a16 + (size_t)d * HID + c) = o;
}

// ---------------- SpMM 64-wide fp16 + bias + log_softmax (final layer) ------
__global__ void __launch_bounds__(256) spmm64_kernel(const float* __restrict__ b3,
                                                     float* __restrict__ out) {
    int t = blockIdx.x * 256 + threadIdx.x;
    int d = t >> 5;
    int lane = t & 31;
    if (d >= NN) return;
    int c = lane * 2;
    int beg = g_rowptr[d], end = g_rowptr[d + 1];
    float a0 = 0.f, a1 = 0.f;
    int j = beg;
    for (; j + 3 < end; j += 4) {
        int s0 = g_col[j], s1 = g_col[j + 1], s2 = g_col[j + 2], s3 = g_col[j + 3];
        float2 v0 = __half22float2(*(const __half2*)(g_z16 + (size_t)s0 * OUTF + c));
        float2 v1 = __half22float2(*(const __half2*)(g_z16 + (size_t)s1 * OUTF + c));
        float2 v2 = __half22float2(*(const __half2*)(g_z16 + (size_t)s2 * OUTF + c));
        float2 v3 = __half22float2(*(const __half2*)(g_z16 + (size_t)s3 * OUTF + c));
        a0 += v0.x + v1.x + v2.x + v3.x;
        a1 += v0.y + v1.y + v2.y + v3.y;
    }
    for (; j < end; j++) {
        int s = g_col[j];
        float2 v = __half22float2(*(const __half2*)(g_z16 + (size_t)s * OUTF + c));
        a0 += v.x; a1 += v.y;
    }
    float nd = g_normd[d];
    a0 = a0 * nd + b3[c];
    a1 = a1 * nd + b3[c + 1];
    float mx = fmaxf(a0, a1);
    #pragma unroll
    for (int off = 16; off > 0; off >>= 1)
        mx = fmaxf(mx, __shfl_xor_sync(0xffffffffu, mx, off));
    float e = expf(a0 - mx) + expf(a1 - mx);
    #pragma unroll
    for (int off = 16; off > 0; off >>= 1)
        e += __shfl_xor_sync(0xffffffffu, e, off);
    float l = logf(e);
    out[(size_t)d * OUTF + c]     = a0 - mx - l;
    out[(size_t)d * OUTF + c + 1] = a1 - mx - l;
}

// ---------------- Tensor-core GEMM (HMMA via wmma) ----------------
// STATS=true  (NC=128): g_t16raw = relu(g_a16 @ W16 + bias); BN stats accum.
// STATS=false (NC=64) : g_z16 = g_a316 @ W16.
// Block = 128 rows x NC cols, 8 warps (16 rows each). Fragments load direct
// from global (A rows private per warp; B 32KB, L1-hot). Epilogue stages
// 128x64 fp32 halves through smem.
template<int NC, bool STATS>
__global__ void __launch_bounds__(256)
gemmtc_kernel(const float* __restrict__ bias, int stats_off) {
    const __half* __restrict__ A = STATS ? g_a16 : g_a316;
    __half* __restrict__ C = STATS ? g_t16raw : g_z16;
    constexpr int NF = NC / 16;

    int w = threadIdx.x >> 5;
    int row0 = blockIdx.x * 128;
    size_t arow = (size_t)(row0 + w * 16);

    wmma::fragment<wmma::accumulator, 16, 16, 16, float> acc[NF];
    #pragma unroll
    for (int n = 0; n < NF; n++) wmma::fill_fragment(acc[n], 0.f);

    #pragma unroll
    for (int k = 0; k < 8; k++) {
        wmma::fragment<wmma::matrix_a, 16, 16, 16, __half, wmma::row_major> af;
        wmma::load_matrix_sync(af, A + arow * HID + k * 16, HID);
        #pragma unroll
        for (int n = 0; n < NF; n++) {
            wmma::fragment<wmma::matrix_b, 16, 16, 16, __half, wmma::row_major> bf;
            wmma::load_matrix_sync(bf, g_w16 + (size_t)k * 16 * NC + n * 16, NC);
            wmma::mma_sync(acc[n], af, bf, acc[n]);
        }
    }

    __shared__ float sC[128 * 64];       // 32 KB
    __shared__ float sstat[2][4][64];    // 2 KB

    #pragma unroll
    for (int half = 0; half < NC / 64; half++) {
        #pragma unroll
        for (int n = 0; n < 4; n++)
            wmma::store_matrix_sync(sC + w * 16 * 64 + n * 16, acc[half * 4 + n],
                                    64, wmma::mem_row_major);
        __syncthreads();

        int col = threadIdx.x & 63;
        int q = threadIdx.x >> 6;        // 0..3, rows q*32..q*32+31
        int gcol = half * 64 + col;
        float bb = STATS ? bias[gcol] : 0.f;
        float ps = 0.f, pq = 0.f;
        #pragma unroll 4
        for (int r = q * 32; r < q * 32 + 32; r++) {
            int grow = row0 + r;
            if (grow < NN) {
                float v = sC[r * 64 + col];
                if (STATS) {
                    v += bb;
                    v = fmaxf(v, 0.f);
                    ps += v;
                    pq += v * v;
                }
                C[(size_t)grow * NC + gcol] = __float2half_rn(v);
            }
        }
        if (STATS) {
            sstat[0][q][col] = ps;
            sstat[1][q][col] = pq;
            __syncthreads();
            if (threadIdx.x < 64) {
                float s = sstat[0][0][threadIdx.x] + sstat[0][1][threadIdx.x]
                        + sstat[0][2][threadIdx.x] + sstat[0][3][threadIdx.x];
                float qq = sstat[1][0][threadIdx.x] + sstat[1][1][threadIdx.x]
                         + sstat[1][2][threadIdx.x] + sstat[1][3][threadIdx.x];
                atomicAdd(&g_stats[stats_off + half * 64 + threadIdx.x], s);
                atomicAdd(&g_stats[stats_off + NC + half * 64 + threadIdx.x], qq);
            }
        }
        __syncthreads();
    }
}

// ---------------- BN finalize ----------------
__global__ void bnfin_kernel(const float* __restrict__ gamma, const float* __restrict__ beta,
                             int stats_off, int which) {
    int c = threadIdx.x;
    if (c < HID) {
        float inv_n = 1.0f / (float)NN;
        float mean = g_stats[stats_off + c] * inv_n;
        float var = g_stats[stats_off + HID + c] * inv_n - mean * mean;
        float sc = gamma[c] * rsqrtf(var + 1e-5f);
        float sh = beta[c] - mean * sc;
        if (which == 1) { g_scale1[c] = sc; g_shift1[c] = sh; }
        else            { g_scale2[c] = sc; g_shift2[c] = sh; }
    }
}

// ---------------- launch ----------------
extern "C" void kernel_launch(void* const* d_in, const int* in_sizes, int n_in,
                              void* d_out, int out_size) {
    const float* x      = (const float*)d_in[0];
    const void*  src    = d_in[1];
    const void*  dst    = d_in[2];
    const float* W1     = (const float*)d_in[3];
    const float* b1     = (const float*)d_in[4];
    const float* W2     = (const float*)d_in[5];
    const float* b2     = (const float*)d_in[6];
    const float* W3     = (const float*)d_in[7];
    const float* b3     = (const float*)d_in[8];
    const float* gamma1 = (const float*)d_in[9];
    const float* beta1  = (const float*)d_in[10];
    const float* gamma2 = (const float*)d_in[11];
    const float* beta2  = (const float*)d_in[12];
    float* out = (float*)d_out;

    const int NB  = (NN + 255) / 256;       // 391
    const int EB  = (NE + 255) / 256;       // 12500
    const int WB  = (NN * 32 + 255) / 256;  // 12500 (warp per node)
    const int GB  = (NN + 127) / 128;       // 782

    init_kernel<<<NB, 256>>>(src);
    degree_kernel<<<EB, 256>>>(src, dst);
    scan_kernel<<<SCAN_NB, 256>>>();
    fill_kernel<<<EB, 256>>>();

    // layer 1
    prepx_kernel<<<WB, 256>>>(x);
    spmm128_f16_kernel<0><<<WB, 256>>>();
    convw_kernel<<<64, 256>>>(W1, HID * HID);
    gemmtc_kernel<128, true><<<GB, 256>>>(b1, 0);
    bnfin_kernel<<<1, 128>>>(gamma1, beta1, 0, 1);

    // layer 2
    prept_kernel<1><<<WB, 256>>>();
    spmm128_f16_kernel<1><<<WB, 256>>>();
    convw_kernel<<<64, 256>>>(W2, HID * HID);
    gemmtc_kernel<128, true><<<GB, 256>>>(b2, 256);
    bnfin_kernel<<<1, 128>>>(gamma2, beta2, 256, 2);

    // layer 3
    prept_kernel<2><<<WB, 256>>>();
    convw_kernel<<<32, 256>>>(W3, HID * OUTF);
    gemmtc_kernel<64, false><<<GB, 256>>>(nullptr, 0);
    spmm64_kernel<<<WB, 256>>>(b3, out);
}

// round 8
// speedup vs baseline: 1.4452x; 1.0577x over previous
#include <cuda_runtime.h>
#include <cuda_fp16.h>
#include <mma.h>
#include <cstdint>

using namespace nvcuda;

#define NN 100000
#define NNP 100096          // 782 * 128, padded for TC GEMM tiles
#define NE 3200000
#define HID 128
#define OUTF 64
#define SCAN_NB 391         // ceil(NN/256)

// ---------------- device scratch (static, zero-initialized, no allocation) --
// Symbols referenced ONLY inside device code (never passed from host).
__device__ int    g_is64;
__device__ int    g_degout[NN];
__device__ int    g_degin[NN];
__device__ float  g_norms[NN];
__device__ float  g_normd[NN];
__device__ float  g_sumns[NN];               // sum of norm_s over in-neighbors
__device__ int    g_rowptr[NN + 1];
__device__ int    g_cnt[NN];
__device__ int    g_srci[NE];
__device__ int    g_dsti[NE];
__device__ int    g_col[NE];
__device__ unsigned long long g_scanstate[SCAN_NB];
__device__ __half g_gat16[(size_t)NNP * HID]; // gather src (x*ns, then v1, then v2); pad rows 0
__device__ __half g_agg16[(size_t)NNP * HID]; // spmm output = GEMM A; pad rows 0
__device__ __half g_z16[(size_t)NN * OUTF];   // layer-3 pre-aggregation
__device__ __half g_w1[HID * HID];
__device__ __half g_w2[HID * HID];
__device__ __half g_w3p[HID * OUTF];          // sc2 ⊙ W3 (fp16)
__device__ float  g_c3[OUTF];                 // sh2 @ W3
__device__ float  g_stats[512];
__device__ float  g_scale1[HID], g_shift1[HID];

// ---------------- init: zero counters, dtype detect, convert W1/W2 ----------
__global__ void init_kernel(const void* src, const float* __restrict__ W1,
                            const float* __restrict__ W2) {
    int i = blockIdx.x * blockDim.x + threadIdx.x;
    if (i < NN) { g_degout[i] = 0; g_degin[i] = 0; }
    if (i < 512) g_stats[i] = 0.f;
    if (i < SCAN_NB) g_scanstate[i] = 0ull;
    if (i < HID * HID) {
        g_w1[i] = __float2half_rn(W1[i]);
        g_w2[i] = __float2half_rn(W2[i]);
    }
    if (i == 0) {
        const long long* p = (const long long*)src;
        int ok = 1;
        #pragma unroll 1
        for (int k = 0; k < 128; k++) {
            long long v = p[k];
            if (v < 0 || v >= NN) { ok = 0; break; }
        }
        g_is64 = ok;
    }
}

// ---------------- degrees + int32 conversion ----------------
__global__ void degree_kernel(const void* src, const void* dst) {
    int e = blockIdx.x * blockDim.x + threadIdx.x;
    if (e >= NE) return;
    int is64 = g_is64;
    int s = is64 ? (int)((const long long*)src)[e] : ((const int*)src)[e];
    int d = is64 ? (int)((const long long*)dst)[e] : ((const int*)dst)[e];
    g_srci[e] = s;
    g_dsti[e] = d;
    atomicAdd(&g_degout[s], 1);
    atomicAdd(&g_degin[d], 1);
}

// ---------------- single-pass scan (decoupled lookback) + norms -------------
__global__ void __launch_bounds__(256) scan_kernel() {
    int bid = blockIdx.x;
    int t = threadIdx.x;
    int lane = t & 31, wid = t >> 5;
    int i = bid * 256 + t;
    int v = (i < NN) ? g_degin[i] : 0;

    int x = v;
    #pragma unroll
    for (int off = 1; off < 32; off <<= 1) {
        int y = __shfl_up_sync(0xffffffffu, x, off);
        if (lane >= off) x += y;
    }
    __shared__ int wsum[8];
    if (lane == 31) wsum[wid] = x;
    __syncthreads();
    if (wid == 0 && lane < 8) {
        int w = wsum[lane];
        #pragma unroll
        for (int off = 1; off < 8; off <<= 1) {
            int y = __shfl_up_sync(0xffu, w, off);
            if (lane >= off) w += y;
        }
        wsum[lane] = w;
    }
    __syncthreads();
    int incl = x + (wid > 0 ? wsum[wid - 1] : 0);
    int bsum = wsum[7];

    __shared__ int s_excl;
    if (t == 0) {
        if (bid == 0) {
            atomicExch(&g_scanstate[0], (2ull << 32) | (unsigned long long)(unsigned)bsum);
            s_excl = 0;
        } else {
            atomicExch(&g_scanstate[bid], (1ull << 32) | (unsigned long long)(unsigned)bsum);
            long long running = 0;
            int j = bid - 1;
            while (true) {
                unsigned long long st = atomicAdd(&g_scanstate[j], 0ull);
                unsigned f = (unsigned)(st >> 32);
                if (f == 0u) continue;
                running += (long long)(unsigned)st;
                if (f == 2u) break;
                j--;
            }
            s_excl = (int)running;
            atomicExch(&g_scanstate[bid],
                       (2ull << 32) | (unsigned long long)(unsigned)(running + bsum));
        }
    }
    __syncthreads();
    int base = s_excl;
    if (i < NN) {
        int r = base + incl - v;
        g_rowptr[i] = r;
        g_cnt[i] = r;
        int dout = g_degout[i]; if (dout < 1) dout = 1;
        int din = v; if (din < 1) din = 1;
        g_norms[i] = rsqrtf((float)dout);
        g_normd[i] = rsqrtf((float)din);
        if (i == NN - 1) g_rowptr[NN] = r + v;
    }
}

__global__ void fill_kernel() {
    int e = blockIdx.x * blockDim.x + threadIdx.x;
    if (e >= NE) return;
    int d = g_dsti[e];
    int pos = atomicAdd(&g_cnt[d], 1);
    g_col[pos] = g_srci[e];
}

// ---------------- sumns[d] = sum of norm_s over in-neighbors ----------------
__global__ void __launch_bounds__(256) sumns_kernel() {
    int t = blockIdx.x * 256 + threadIdx.x;
    int d = t >> 5;
    int lane = t & 31;
    if (d >= NN) return;
    int beg = g_rowptr[d], end = g_rowptr[d + 1];
    float s = 0.f;
    for (int j = beg + lane; j < end; j += 32)
        s += g_norms[g_col[j]];
    #pragma unroll
    for (int off = 16; off > 0; off >>= 1)
        s += __shfl_xor_sync(0xffffffffu, s, off);
    if (lane == 0) g_sumns[d] = s;
}

// ---------------- prep: gat16 = x * norm_s (fp16) ----------------
__global__ void __launch_bounds__(256) prepx_kernel(const float* __restrict__ in) {
    int t = blockIdx.x * 256 + threadIdx.x;
    int node = t >> 5;
    if (node >= NN) return;
    int c = (t & 31) * 4;
    float ns = g_norms[node];
    float4 v = *(const float4*)(in + (size_t)node * HID + c);
    __half2 h0 = __floats2half2_rn(v.x * ns, v.y * ns);
    __half2 h1 = __floats2half2_rn(v.z * ns, v.w * ns);
    uint2 u;
    u.x = *(unsigned*)&h0;
    u.y = *(unsigned*)&h1;
    *(uint2*)(g_gat16 + (size_t)node * HID + c) = u;
}

// ---------------- SpMM: warp per dst node, fp16 gather, pairwise hadd2 ------
// AFFINE=false (layer 1): m = S * nd
// AFFINE=true  (layer 2): m = (sc1 ⊙ S + sh1 * sumns[d]) * nd
template<bool AFFINE>
__global__ void __launch_bounds__(256) spmm128_kernel() {
    int t = blockIdx.x * 256 + threadIdx.x;
    int d = t >> 5;
    int lane = t & 31;
    if (d >= NN) return;
    int c = lane * 4;
    int beg = g_rowptr[d], end = g_rowptr[d + 1];
    float ax = 0.f, ay = 0.f, az = 0.f, aw = 0.f;
    int j = beg;
    for (; j + 3 < end; j += 4) {
        int s0 = g_col[j], s1 = g_col[j + 1], s2 = g_col[j + 2], s3 = g_col[j + 3];
        uint2 u0 = *(const uint2*)(g_gat16 + (size_t)s0 * HID + c);
        uint2 u1 = *(const uint2*)(g_gat16 + (size_t)s1 * HID + c);
        uint2 u2 = *(const uint2*)(g_gat16 + (size_t)s2 * HID + c);
        uint2 u3 = *(const uint2*)(g_gat16 + (size_t)s3 * HID + c);
        // one-level pairwise fp16 adds, then fp32 accumulate
        __half2 p0 = __hadd2(*(__half2*)&u0.x, *(__half2*)&u1.x);
        __half2 q0 = __hadd2(*(__half2*)&u2.x, *(__half2*)&u3.x);
        __half2 p1 = __hadd2(*(__half2*)&u0.y, *(__half2*)&u1.y);
        __half2 q1 = __hadd2(*(__half2*)&u2.y, *(__half2*)&u3.y);
        float2 f;
        f = __half22float2(p0); ax += f.x; ay += f.y;
        f = __half22float2(q0); ax += f.x; ay += f.y;
        f = __half22float2(p1); az += f.x; aw += f.y;
        f = __half22float2(q1); az += f.x; aw += f.y;
    }
    for (; j < end; j++) {
        int s = g_col[j];
        uint2 u = *(const uint2*)(g_gat16 + (size_t)s * HID + c);
        float2 a = __half22float2(*(__half2*)&u.x), b = __half22float2(*(__half2*)&u.y);
        ax += a.x; ay += a.y; az += b.x; aw += b.y;
    }
    float nd = g_normd[d];
    if (AFFINE) {
        float4 sc = *(const float4*)(g_scale1 + c);
        float4 sh = *(const float4*)(g_shift1 + c);
        float sn = g_sumns[d];
        ax = fmaf(sh.x, sn, ax * sc.x);
        ay = fmaf(sh.y, sn, ay * sc.y);
        az = fmaf(sh.z, sn, az * sc.z);
        aw = fmaf(sh.w, sn, aw * sc.w);
    }
    __half2 h0 = __floats2half2_rn(ax * nd, ay * nd);
    __half2 h1 = __floats2half2_rn(az * nd, aw * nd);
    uint2 o;
    o.x = *(unsigned*)&h0;
    o.y = *(unsigned*)&h1;
    *(uint2*)(g_agg16 + (size_t)d * HID + c) = o;
}

// ---------------- SpMM 64-wide + c3*sumns + bias + log_softmax --------------
__global__ void __launch_bounds__(256) spmm64_kernel(const float* __restrict__ b3,
                                                     float* __restrict__ out) {
    int t = blockIdx.x * 256 + threadIdx.x;
    int d = t >> 5;
    int lane = t & 31;
    if (d >= NN) return;
    int c = lane * 2;
    int beg = g_rowptr[d], end = g_rowptr[d + 1];
    float a0 = 0.f, a1 = 0.f;
    int j = beg;
    for (; j + 3 < end; j += 4) {
        int s0 = g_col[j], s1 = g_col[j + 1], s2 = g_col[j + 2], s3 = g_col[j + 3];
        __half2 v0 = *(const __half2*)(g_z16 + (size_t)s0 * OUTF + c);
        __half2 v1 = *(const __half2*)(g_z16 + (size_t)s1 * OUTF + c);
        __half2 v2 = *(const __half2*)(g_z16 + (size_t)s2 * OUTF + c);
        __half2 v3 = *(const __half2*)(g_z16 + (size_t)s3 * OUTF + c);
        float2 f01 = __half22float2(__hadd2(v0, v1));
        float2 f23 = __half22float2(__hadd2(v2, v3));
        a0 += f01.x + f23.x;
        a1 += f01.y + f23.y;
    }
    for (; j < end; j++) {
        int s = g_col[j];
        float2 v = __half22float2(*(const __half2*)(g_z16 + (size_t)s * OUTF + c));
        a0 += v.x; a1 += v.y;
    }
    float nd = g_normd[d];
    float sn = g_sumns[d];
    a0 = (a0 + g_c3[c] * sn) * nd + b3[c];
    a1 = (a1 + g_c3[c + 1] * sn) * nd + b3[c + 1];
    float mx = fmaxf(a0, a1);
    #pragma unroll
    for (int off = 16; off > 0; off >>= 1)
        mx = fmaxf(mx, __shfl_xor_sync(0xffffffffu, mx, off));
    float e = expf(a0 - mx) + expf(a1 - mx);
    #pragma unroll
    for (int off = 16; off > 0; off >>= 1)
        e += __shfl_xor_sync(0xffffffffu, e, off);
    float l = logf(e);
    out[(size_t)d * OUTF + c]     = a0 - mx - l;
    out[(size_t)d * OUTF + c + 1] = a1 - mx - l;
}

// ---------------- Tensor-core GEMM (HMMA via wmma), B staged in smem --------
// L=0: v1 = relu(agg @ W1 + b1)*ns -> gat16; stats@0
// L=1: v2 = relu(agg @ W2 + b2)*ns -> gat16; stats@256
// L=2: z' = gat16 @ W3'            -> z16
template<int L>
__global__ void __launch_bounds__(256)
gemmtc_kernel(const float* __restrict__ bias) {
    constexpr bool STATS = (L < 2);
    constexpr int NC = STATS ? HID : OUTF;
    constexpr int NF = NC / 16;
    const __half* __restrict__ A = STATS ? g_agg16 : g_gat16;
    const __half* __restrict__ W = (L == 0) ? g_w1 : (L == 1) ? g_w2 : g_w3p;
    __half* __restrict__ C = STATS ? g_gat16 : g_z16;
    const int stats_off = (L == 1) ? 256 : 0;

    __shared__ __align__(16) unsigned char sraw[128 * 64 * 4]; // 32KB: sB then sC
    __shared__ float sstat[2][4][64];
    __half* sB = (__half*)sraw;
    float* sC = (float*)sraw;

    int tid = threadIdx.x;
    int w = tid >> 5;
    int row0 = blockIdx.x * 128;
    size_t arow = (size_t)(row0 + w * 16);

    // stage B (HID x NC fp16) into smem
    constexpr int NB16 = HID * NC / 8;   // uint4 chunks
    #pragma unroll
    for (int l = tid; l < NB16; l += 256)
        *(uint4*)(sB + l * 8) = *(const uint4*)(W + (size_t)l * 8);
    __syncthreads();

    wmma::fragment<wmma::accumulator, 16, 16, 16, float> acc[NF];
    #pragma unroll
    for (int n = 0; n < NF; n++) wmma::fill_fragment(acc[n], 0.f);

    #pragma unroll
    for (int k = 0; k < 8; k++) {
        wmma::fragment<wmma::matrix_a, 16, 16, 16, __half, wmma::row_major> af;
        wmma::load_matrix_sync(af, A + arow * HID + k * 16, HID);
        #pragma unroll
        for (int n = 0; n < NF; n++) {
            wmma::fragment<wmma::matrix_b, 16, 16, 16, __half, wmma::row_major> bf;
            wmma::load_matrix_sync(bf, sB + k * 16 * NC + n * 16, NC);
            wmma::mma_sync(acc[n], af, bf, acc[n]);
        }
    }
    __syncthreads();   // done with sB; sC reuses the space

    #pragma unroll
    for (int half = 0; half < NC / 64; half++) {
        #pragma unroll
        for (int n = 0; n < 4; n++)
            wmma::store_matrix_sync(sC + w * 16 * 64 + n * 16, acc[half * 4 + n],
                                    64, wmma::mem_row_major);
        __syncthreads();

        int col = tid & 63;
        int q = tid >> 6;            // 0..3, rows q*32..q*32+31
        int gcol = half * 64 + col;
        float bb = STATS ? bias[gcol] : 0.f;
        float ps = 0.f, pq = 0.f;
        #pragma unroll 4
        for (int r = q * 32; r < q * 32 + 32; r++) {
            int grow = row0 + r;
            if (grow < NN) {
                float v = sC[r * 64 + col];
                if (STATS) {
                    v += bb;
                    v = fmaxf(v, 0.f);
                    ps += v;
                    pq += v * v;
                    v *= g_norms[grow];  // fold norm_s into stored operand
                }
                C[(size_t)grow * NC + gcol] = __float2half_rn(v);
            }
        }
        if (STATS) {
            sstat[0][q][col] = ps;
            sstat[1][q][col] = pq;
            __syncthreads();
            if (tid < 64) {
                float s = sstat[0][0][tid] + sstat[0][1][tid]
                        + sstat[0][2][tid] + sstat[0][3][tid];
                float qq = sstat[1][0][tid] + sstat[1][1][tid]
                         + sstat[1][2][tid] + sstat[1][3][tid];
                atomicAdd(&g_stats[stats_off + half * 64 + tid], s);
                atomicAdd(&g_stats[stats_off + NC + half * 64 + tid], qq);
            }
        }
        __syncthreads();
    }
}

// ---------------- BN1 finalize ----------------
__global__ void bnfin1_kernel(const float* __restrict__ gamma, const float* __restrict__ beta) {
    int c = threadIdx.x;
    if (c < HID) {
        float inv_n = 1.0f / (float)NN;
        float mean = g_stats[c] * inv_n;
        float var = g_stats[HID + c] * inv_n - mean * mean;
        float sc = gamma[c] * rsqrtf(var + 1e-5f);
        g_scale1[c] = sc;
        g_shift1[c] = beta[c] - mean * sc;
    }
}

// ---------------- BN2 finalize + W3' + c3 ----------------
__global__ void finalize2_kernel(const float* __restrict__ gamma, const float* __restrict__ beta,
                                 const float* __restrict__ W3) {
    __shared__ float ssh[HID];
    int t = threadIdx.x;  // 128
    float inv_n = 1.0f / (float)NN;
    float mean = g_stats[256 + t] * inv_n;
    float var = g_stats[256 + HID + t] * inv_n - mean * mean;
    float sc = gamma[t] * rsqrtf(var + 1e-5f);
    float sh = beta[t] - mean * sc;
    ssh[t] = sh;
    __syncthreads();
    // W3' row t
    #pragma unroll 4
    for (int n = 0; n < OUTF; n++)
        g_w3p[t * OUTF + n] = __float2half_rn(sc * W3[t * OUTF + n]);
    // c3[n] = sum_k sh[k] * W3[k][n]
    if (t < OUTF) {
        float cc = 0.f;
        #pragma unroll 4
        for (int k = 0; k < HID; k++)
            cc += ssh[k] * W3[k * OUTF + t];
        g_c3[t] = cc;
    }
}

// ---------------- launch ----------------
extern "C" void kernel_launch(void* const* d_in, const int* in_sizes, int n_in,
                              void* d_out, int out_size) {
    const float* x      = (const float*)d_in[0];
    const void*  src    = d_in[1];
    const void*  dst    = d_in[2];
    const float* W1     = (const float*)d_in[3];
    const float* b1     = (const float*)d_in[4];
    const float* W2     = (const float*)d_in[5];
    const float* b2     = (const float*)d_in[6];
    const float* W3     = (const float*)d_in[7];
    const float* b3     = (const float*)d_in[8];
    const float* gamma1 = (const float*)d_in[9];
    const float* beta1  = (const float*)d_in[10];
    const float* gamma2 = (const float*)d_in[11];
    const float* beta2  = (const float*)d_in[12];
    float* out = (float*)d_out;

    const int NB  = (NN + 255) / 256;       // 391
    const int EB  = (NE + 255) / 256;       // 12500
    const int WB  = (NN * 32 + 255) / 256;  // 12500 (warp per node)
    const int GB  = (NN + 127) / 128;       // 782

    init_kernel<<<NB, 256>>>(src, W1, W2);
    degree_kernel<<<EB, 256>>>(src, dst);
    scan_kernel<<<SCAN_NB, 256>>>();
    fill_kernel<<<EB, 256>>>();
    sumns_kernel<<<WB, 256>>>();

    // layer 1
    prepx_kernel<<<WB, 256>>>(x);
    spmm128_kernel<false><<<WB, 256>>>();
    gemmtc_kernel<0><<<GB, 256>>>(b1);
    bnfin1_kernel<<<1, 128>>>(gamma1, beta1);

    // layer 2 (affine applied in spmm epilogue via sumns)
    spmm128_kernel<true><<<WB, 256>>>();
    gemmtc_kernel<1><<<GB, 256>>>(b2);
    finalize2_kernel<<<1, 128>>>(gamma2, beta2, W3);

    // layer 3
    gemmtc_kernel<2><<<GB, 256>>>(nullptr);
    spmm64_kernel<<<WB, 256>>>(b3, out);
}

// round 9
// speedup vs baseline: 1.4624x; 1.0119x over previous
#include <cuda_runtime.h>
#include <cuda_fp16.h>
#include <mma.h>
#include <cstdint>

using namespace nvcuda;

#define NN 100000
#define NNP 100096          // 782 * 128, padded for TC GEMM tiles
#define NE 3200000
#define HID 128
#define OUTF 64
#define SCAN_NB 391         // ceil(NN/256)
#define EB 12500            // NE/256 edge blocks (fill part)
#define WB 12500            // warp-per-node blocks

// ---------------- device scratch (static, no allocation) ----------------
// Symbols referenced ONLY inside device code (never passed as kernel args
// from host). Zeroed-per-run state packed into one struct for a single memset.
struct ZeroBlk {
    int   degout[NN];
    int   degin[NN];
    float sumns[NN];                 // sum of norm_s over in-neighbors
    float stats[512];
    unsigned long long scanstate[SCAN_NB];
};
__device__ ZeroBlk g_zb;

__device__ int    g_is64;
__device__ float  g_norms[NN];
__device__ float  g_normd[NN];
__device__ int    g_rowptr[NN + 1];
__device__ int    g_cnt[NN];
__device__ int    g_srci[NE];
__device__ int    g_dsti[NE];
__device__ int    g_col[NE];
__device__ __half g_gat16[(size_t)NNP * HID]; // gather src (x*ns -> v1 -> v2); pad rows 0
__device__ __half g_agg16[(size_t)NNP * HID]; // spmm output = GEMM A; pad rows 0
__device__ __half g_z16[(size_t)NN * OUTF];   // layer-3 pre-aggregation
__device__ __half g_w1[HID * HID];
__device__ __half g_w2[HID * HID];
__device__ __half g_w3p[HID * OUTF];          // sc2 ⊙ W3 (fp16)
__device__ float  g_c3[OUTF];                 // sh2 @ W3
__device__ float  g_scale1[HID], g_shift1[HID];

// ---------------- detect dtype + convert W1/W2 to fp16 ----------------
__global__ void detectconv_kernel(const void* src, const float* __restrict__ W1,
                                  const float* __restrict__ W2) {
    int i = blockIdx.x * blockDim.x + threadIdx.x;   // 64*256 = 16384 = HID*HID
    g_w1[i] = __float2half_rn(W1[i]);
    g_w2[i] = __float2half_rn(W2[i]);
    if (i == 0) {
        const long long* p = (const long long*)src;
        int ok = 1;
        #pragma unroll 1
        for (int k = 0; k < 128; k++) {
            long long v = p[k];
            if (v < 0 || v >= NN) { ok = 0; break; }
        }
        g_is64 = ok;
    }
}

// ---------------- degrees + int32 conversion (2 edges/thread) ---------------
__global__ void __launch_bounds__(256) degree_kernel(const void* src, const void* dst) {
    int p = blockIdx.x * blockDim.x + threadIdx.x;   // pair index
    int e = p * 2;
    if (e >= NE) return;
    int s0, s1, d0, d1;
    if (g_is64) {
        longlong2 a = ((const longlong2*)src)[p];
        longlong2 b = ((const longlong2*)dst)[p];
        s0 = (int)a.x; s1 = (int)a.y;
        d0 = (int)b.x; d1 = (int)b.y;
    } else {
        int2 a = ((const int2*)src)[p];
        int2 b = ((const int2*)dst)[p];
        s0 = a.x; s1 = a.y;
        d0 = b.x; d1 = b.y;
    }
    *(int2*)(g_srci + e) = make_int2(s0, s1);
    *(int2*)(g_dsti + e) = make_int2(d0, d1);
    atomicAdd(&g_zb.degout[s0], 1);
    atomicAdd(&g_zb.degout[s1], 1);
    atomicAdd(&g_zb.degin[d0], 1);
    atomicAdd(&g_zb.degin[d1], 1);
}

// ---------------- single-pass scan (decoupled lookback) + norms -------------
__global__ void __launch_bounds__(256) scan_kernel() {
    int bid = blockIdx.x;
    int t = threadIdx.x;
    int lane = t & 31, wid = t >> 5;
    int i = bid * 256 + t;
    int v = (i < NN) ? g_zb.degin[i] : 0;

    int x = v;
    #pragma unroll
    for (int off = 1; off < 32; off <<= 1) {
        int y = __shfl_up_sync(0xffffffffu, x, off);
        if (lane >= off) x += y;
    }
    __shared__ int wsum[8];
    if (lane == 31) wsum[wid] = x;
    __syncthreads();
    if (wid == 0 && lane < 8) {
        int w = wsum[lane];
        #pragma unroll
        for (int off = 1; off < 8; off <<= 1) {
            int y = __shfl_up_sync(0xffu, w, off);
            if (lane >= off) w += y;
        }
        wsum[lane] = w;
    }
    __syncthreads();
    int incl = x + (wid > 0 ? wsum[wid - 1] : 0);
    int bsum = wsum[7];

    __shared__ int s_excl;
    if (t == 0) {
        if (bid == 0) {
            atomicExch(&g_zb.scanstate[0], (2ull << 32) | (unsigned long long)(unsigned)bsum);
            s_excl = 0;
        } else {
            atomicExch(&g_zb.scanstate[bid], (1ull << 32) | (unsigned long long)(unsigned)bsum);
            long long running = 0;
            int j = bid - 1;
            while (true) {
                unsigned long long st = atomicAdd(&g_zb.scanstate[j], 0ull);
                unsigned f = (unsigned)(st >> 32);
                if (f == 0u) continue;
                running += (long long)(unsigned)st;
                if (f == 2u) break;
                j--;
            }
            s_excl = (int)running;
            atomicExch(&g_zb.scanstate[bid],
                       (2ull << 32) | (unsigned long long)(unsigned)(running + bsum));
        }
    }
    __syncthreads();
    int base = s_excl;
    if (i < NN) {
        int r = base + incl - v;
        g_rowptr[i] = r;
        g_cnt[i] = r;
        int dout = g_zb.degout[i]; if (dout < 1) dout = 1;
        int din = v; if (din < 1) din = 1;
        g_norms[i] = rsqrtf((float)dout);
        g_normd[i] = rsqrtf((float)din);
        if (i == NN - 1) g_rowptr[NN] = r + v;
    }
}

// ---------------- fused: CSR fill + sumns atomics + prepx -------------------
// blocks [0, EB)       : edge work — fill g_col, accumulate sumns
// blocks [EB, EB+WB)   : node work — gat16 = x * norm_s (fp16)
__global__ void __launch_bounds__(256) fillprep_kernel(const float* __restrict__ x) {
    int b = blockIdx.x;
    if (b < EB) {
        int e = b * 256 + threadIdx.x;
        int s = g_srci[e];
        int d = g_dsti[e];
        int pos = atomicAdd(&g_cnt[d], 1);
        g_col[pos] = s;
        atomicAdd(&g_zb.sumns[d], g_norms[s]);
    } else {
        int t = (b - EB) * 256 + threadIdx.x;
        int node = t >> 5;
        if (node >= NN) return;
        int c = (t & 31) * 4;
        float ns = g_norms[node];
        float4 v = *(const float4*)(x + (size_t)node * HID + c);
        __half2 h0 = __floats2half2_rn(v.x * ns, v.y * ns);
        __half2 h1 = __floats2half2_rn(v.z * ns, v.w * ns);
        uint2 u;
        u.x = *(unsigned*)&h0;
        u.y = *(unsigned*)&h1;
        *(uint2*)(g_gat16 + (size_t)node * HID + c) = u;
    }
}

// ---------------- SpMM: warp per dst node, fp16 gather, pairwise hadd2 ------
// AFFINE=false (layer 1): m = S * nd
// AFFINE=true  (layer 2): m = (sc1 ⊙ S + sh1 * sumns[d]) * nd
template<bool AFFINE>
__global__ void __launch_bounds__(256) spmm128_kernel() {
    int t = blockIdx.x * 256 + threadIdx.x;
    int d = t >> 5;
    int lane = t & 31;
    if (d >= NN) return;
    int c = lane * 4;
    int beg = g_rowptr[d], end = g_rowptr[d + 1];
    float ax = 0.f, ay = 0.f, az = 0.f, aw = 0.f;
    int j = beg;
    for (; j + 3 < end; j += 4) {
        int s0 = g_col[j], s1 = g_col[j + 1], s2 = g_col[j + 2], s3 = g_col[j + 3];
        uint2 u0 = *(const uint2*)(g_gat16 + (size_t)s0 * HID + c);
        uint2 u1 = *(const uint2*)(g_gat16 + (size_t)s1 * HID + c);
        uint2 u2 = *(const uint2*)(g_gat16 + (size_t)s2 * HID + c);
        uint2 u3 = *(const uint2*)(g_gat16 + (size_t)s3 * HID + c);
        __half2 p0 = __hadd2(*(__half2*)&u0.x, *(__half2*)&u1.x);
        __half2 q0 = __hadd2(*(__half2*)&u2.x, *(__half2*)&u3.x);
        __half2 p1 = __hadd2(*(__half2*)&u0.y, *(__half2*)&u1.y);
        __half2 q1 = __hadd2(*(__half2*)&u2.y, *(__half2*)&u3.y);
        float2 f;
        f = __half22float2(p0); ax += f.x; ay += f.y;
        f = __half22float2(q0); ax += f.x; ay += f.y;
        f = __half22float2(p1); az += f.x; aw += f.y;
        f = __half22float2(q1); az += f.x; aw += f.y;
    }
    for (; j < end; j++) {
        int s = g_col[j];
        uint2 u = *(const uint2*)(g_gat16 + (size_t)s * HID + c);
        float2 a = __half22float2(*(__half2*)&u.x), b = __half22float2(*(__half2*)&u.y);
        ax += a.x; ay += a.y; az += b.x; aw += b.y;
    }
    float nd = g_normd[d];
    if (AFFINE) {
        float4 sc = *(const float4*)(g_scale1 + c);
        float4 sh = *(const float4*)(g_shift1 + c);
        float sn = g_zb.sumns[d];
        ax = fmaf(sh.x, sn, ax * sc.x);
        ay = fmaf(sh.y, sn, ay * sc.y);
        az = fmaf(sh.z, sn, az * sc.z);
        aw = fmaf(sh.w, sn, aw * sc.w);
    }
    __half2 h0 = __floats2half2_rn(ax * nd, ay * nd);
    __half2 h1 = __floats2half2_rn(az * nd, aw * nd);
    uint2 o;
    o.x = *(unsigned*)&h0;
    o.y = *(unsigned*)&h1;
    *(uint2*)(g_agg16 + (size_t)d * HID + c) = o;
}

// ---------------- SpMM 64-wide + c3*sumns + bias + log_softmax --------------
__global__ void __launch_bounds__(256) spmm64_kernel(const float* __restrict__ b3,
                                                     float* __restrict__ out) {
    int t = blockIdx.x * 256 + threadIdx.x;
    int d = t >> 5;
    int lane = t & 31;
    if (d >= NN) return;
    int c = lane * 2;
    int beg = g_rowptr[d], end = g_rowptr[d + 1];
    float a0 = 0.f, a1 = 0.f;
    int j = beg;
    for (; j + 3 < end; j += 4) {
        int s0 = g_col[j], s1 = g_col[j + 1], s2 = g_col[j + 2], s3 = g_col[j + 3];
        __half2 v0 = *(const __half2*)(g_z16 + (size_t)s0 * OUTF + c);
        __half2 v1 = *(const __half2*)(g_z16 + (size_t)s1 * OUTF + c);
        __half2 v2 = *(const __half2*)(g_z16 + (size_t)s2 * OUTF + c);
        __half2 v3 = *(const __half2*)(g_z16 + (size_t)s3 * OUTF + c);
        float2 f01 = __half22float2(__hadd2(v0, v1));
        float2 f23 = __half22float2(__hadd2(v2, v3));
        a0 += f01.x + f23.x;
        a1 += f01.y + f23.y;
    }
    for (; j < end; j++) {
        int s = g_col[j];
        float2 v = __half22float2(*(const __half2*)(g_z16 + (size_t)s * OUTF + c));
        a0 += v.x; a1 += v.y;
    }
    float nd = g_normd[d];
    float sn = g_zb.sumns[d];
    a0 = (a0 + g_c3[c] * sn) * nd + b3[c];
    a1 = (a1 + g_c3[c + 1] * sn) * nd + b3[c + 1];
    float mx = fmaxf(a0, a1);
    #pragma unroll
    for (int off = 16; off > 0; off >>= 1)
        mx = fmaxf(mx, __shfl_xor_sync(0xffffffffu, mx, off));
    float e = expf(a0 - mx) + expf(a1 - mx);
    #pragma unroll
    for (int off = 16; off > 0; off >>= 1)
        e += __shfl_xor_sync(0xffffffffu, e, off);
    float l = logf(e);
    out[(size_t)d * OUTF + c]     = a0 - mx - l;
    out[(size_t)d * OUTF + c + 1] = a1 - mx - l;
}

// ---------------- Tensor-core GEMM (HMMA via wmma), B staged in smem --------
// L=0: v1 = relu(agg @ W1 + b1)*ns -> gat16; stats@0
// L=1: v2 = relu(agg @ W2 + b2)*ns -> gat16; stats@256
// L=2: z' = gat16 @ W3'            -> z16
template<int L>
__global__ void __launch_bounds__(256)
gemmtc_kernel(const float* __restrict__ bias) {
    constexpr bool STATS = (L < 2);
    constexpr int NC = STATS ? HID : OUTF;
    constexpr int NF = NC / 16;
    const __half* __restrict__ A = STATS ? g_agg16 : g_gat16;
    const __half* __restrict__ W = (L == 0) ? g_w1 : (L == 1) ? g_w2 : g_w3p;
    __half* __restrict__ C = STATS ? g_gat16 : g_z16;
    const int stats_off = (L == 1) ? 256 : 0;

    __shared__ __align__(16) unsigned char sraw[128 * 64 * 4]; // 32KB: sB then sC
    __shared__ float sstat[2][4][64];
    __half* sB = (__half*)sraw;
    float* sC = (float*)sraw;

    int tid = threadIdx.x;
    int w = tid >> 5;
    int row0 = blockIdx.x * 128;
    size_t arow = (size_t)(row0 + w * 16);

    constexpr int NB16 = HID * NC / 8;
    #pragma unroll
    for (int l = tid; l < NB16; l += 256)
        *(uint4*)(sB + l * 8) = *(const uint4*)(W + (size_t)l * 8);
    __syncthreads();

    wmma::fragment<wmma::accumulator, 16, 16, 16, float> acc[NF];
    #pragma unroll
    for (int n = 0; n < NF; n++) wmma::fill_fragment(acc[n], 0.f);

    #pragma unroll
    for (int k = 0; k < 8; k++) {
        wmma::fragment<wmma::matrix_a, 16, 16, 16, __half, wmma::row_major> af;
        wmma::load_matrix_sync(af, A + arow * HID + k * 16, HID);
        #pragma unroll
        for (int n = 0; n < NF; n++) {
            wmma::fragment<wmma::matrix_b, 16, 16, 16, __half, wmma::row_major> bf;
            wmma::load_matrix_sync(bf, sB + k * 16 * NC + n * 16, NC);
            wmma::mma_sync(acc[n], af, bf, acc[n]);
        }
    }
    __syncthreads();   // done with sB; sC reuses the space

    #pragma unroll
    for (int half = 0; half < NC / 64; half++) {
        #pragma unroll
        for (int n = 0; n < 4; n++)
            wmma::store_matrix_sync(sC + w * 16 * 64 + n * 16, acc[half * 4 + n],
                                    64, wmma::mem_row_major);
        __syncthreads();

        int col = tid & 63;
        int q = tid >> 6;
        int gcol = half * 64 + col;
        float bb = STATS ? bias[gcol] : 0.f;
        float ps = 0.f, pq = 0.f;
        #pragma unroll 4
        for (int r = q * 32; r < q * 32 + 32; r++) {
            int grow = row0 + r;
            if (grow < NN) {
                float v = sC[r * 64 + col];
                if (STATS) {
                    v += bb;
                    v = fmaxf(v, 0.f);
                    ps += v;
                    pq += v * v;
                    v *= g_norms[grow];  // fold norm_s into stored operand
                }
                C[(size_t)grow * NC + gcol] = __float2half_rn(v);
            }
        }
        if (STATS) {
            sstat[0][q][col] = ps;
            sstat[1][q][col] = pq;
            __syncthreads();
            if (tid < 64) {
                float s = sstat[0][0][tid] + sstat[0][1][tid]
                        + sstat[0][2][tid] + sstat[0][3][tid];
                float qq = sstat[1][0][tid] + sstat[1][1][tid]
                         + sstat[1][2][tid] + sstat[1][3][tid];
                atomicAdd(&g_zb.stats[stats_off + half * 64 + tid], s);
                atomicAdd(&g_zb.stats[stats_off + NC + half * 64 + tid], qq);
            }
        }
        __syncthreads();
    }
}

// ---------------- BN1 finalize ----------------
__global__ void bnfin1_kernel(const float* __restrict__ gamma, const float* __restrict__ beta) {
    int c = threadIdx.x;
    if (c < HID) {
        float inv_n = 1.0f / (float)NN;
        float mean = g_zb.stats[c] * inv_n;
        float var = g_zb.stats[HID + c] * inv_n - mean * mean;
        float sc = gamma[c] * rsqrtf(var + 1e-5f);
        g_scale1[c] = sc;
        g_shift1[c] = beta[c] - mean * sc;
    }
}

// ---------------- BN2 finalize + W3' + c3 ----------------
__global__ void finalize2_kernel(const float* __restrict__ gamma, const float* __restrict__ beta,
                                 const float* __restrict__ W3) {
    __shared__ float ssh[HID];
    int t = threadIdx.x;  // 128
    float inv_n = 1.0f / (float)NN;
    float mean = g_zb.stats[256 + t] * inv_n;
    float var = g_zb.stats[256 + HID + t] * inv_n - mean * mean;
    float sc = gamma[t] * rsqrtf(var + 1e-5f);
    float sh = beta[t] - mean * sc;
    ssh[t] = sh;
    __syncthreads();
    #pragma unroll 4
    for (int n = 0; n < OUTF; n++)
        g_w3p[t * OUTF + n] = __float2half_rn(sc * W3[t * OUTF + n]);
    if (t < OUTF) {
        float cc = 0.f;
        #pragma unroll 4
        for (int k = 0; k < HID; k++)
            cc += ssh[k] * W3[k * OUTF + t];
        g_c3[t] = cc;
    }
}

// ---------------- launch ----------------
extern "C" void kernel_launch(void* const* d_in, const int* in_sizes, int n_in,
                              void* d_out, int out_size) {
    const float* x      = (const float*)d_in[0];
    const void*  src    = d_in[1];
    const void*  dst    = d_in[2];
    const float* W1     = (const float*)d_in[3];
    const float* b1     = (const float*)d_in[4];
    const float* W2     = (const float*)d_in[5];
    const float* b2     = (const float*)d_in[6];
    const float* W3     = (const float*)d_in[7];
    const float* b3     = (const float*)d_in[8];
    const float* gamma1 = (const float*)d_in[9];
    const float* beta1  = (const float*)d_in[10];
    const float* gamma2 = (const float*)d_in[11];
    const float* beta2  = (const float*)d_in[12];
    float* out = (float*)d_out;

    const int EB2 = (NE / 2 + 255) / 256;   // 6250 (2 edges/thread)
    const int GB  = (NN + 127) / 128;       // 782

    // one memset zeroes all per-run accumulators (graph-capturable memset node)
    void* zb = nullptr;
    cudaGetSymbolAddress(&zb, g_zb);
    cudaMemsetAsync(zb, 0, sizeof(ZeroBlk), 0);

    detectconv_kernel<<<64, 256>>>(src, W1, W2);
    degree_kernel<<<EB2, 256>>>(src, dst);
    scan_kernel<<<SCAN_NB, 256>>>();
    fillprep_kernel<<<EB + WB, 256>>>(x);

    // layer 1
    spmm128_kernel<false><<<WB, 256>>>();
    gemmtc_kernel<0><<<GB, 256>>>(b1);
    bnfin1_kernel<<<1, 128>>>(gamma1, beta1);

    // layer 2 (BN1 affine via sumns in spmm epilogue)
    spmm128_kernel<true><<<WB, 256>>>();
    gemmtc_kernel<1><<<GB, 256>>>(b2);
    finalize2_kernel<<<1, 128>>>(gamma2, beta2, W3);

    // layer 3
    gemmtc_kernel<2><<<GB, 256>>>(nullptr);
    spmm64_kernel<<<WB, 256>>>(b3, out);
}